// round 1
// baseline (speedup 1.0000x reference)
#include <cuda_runtime.h>
#include <cuda_bf16.h>
#include <math.h>

// Problem constants
#define BATCH 8
#define NSEQ  4096
#define FDIM  1024
#define LDIM  256
#define ODIM  1024

// Scratch (device globals; no allocation allowed)
__device__ float g_C[BATCH * FDIM * FDIM];   // x^T x        [8,1024,1024]
__device__ float g_P[BATCH * LDIM * FDIM];   // W_phi C      [8,256,1024]
__device__ float g_Q[BATCH * LDIM * ODIM];   // P W_g^T      [8,256,1024]
__device__ float g_R[BATCH * FDIM * ODIM];   // W_th^T Q     [8,1024,1024]

// ----------------------------------------------------------------------------
// Generic tiled SGEMM: D[M,N] = alpha * sum_k Aop[m,k] * Bop[k,n]  (batched)
//   TA=false: A stored row-major [M,K];  TA=true: A stored [K,M]
//   TB=false: B stored row-major [K,N];  TB=true: B stored [N,K]
// Requires M,N multiples of 128 and K multiple of 16 (true for all 5 calls).
// Block tile 128x128, K-tile 16, 256 threads, 8x8 per-thread micro-tile.
// ----------------------------------------------------------------------------
template <bool TA, bool TB>
__global__ __launch_bounds__(256)
void sgemm_kernel(const float* __restrict__ A, const float* __restrict__ B,
                  float* __restrict__ D,
                  int M, int N, int K,
                  long long sA, long long sB, long long sD, float alpha)
{
    constexpr int BM = 128, BN = 128, BK = 16;
    __shared__ float As[BK][BM];
    __shared__ float Bs[BK][BN];

    const int b = blockIdx.z;
    A += (long long)b * sA;
    B += (long long)b * sB;
    D += (long long)b * sD;

    const int m0 = blockIdx.y * BM;
    const int n0 = blockIdx.x * BN;
    const int tid = threadIdx.x;
    const int tx = tid & 15;          // 0..15 (N direction)
    const int ty = tid >> 4;          // 0..15 (M direction)

    float acc[8][8];
#pragma unroll
    for (int i = 0; i < 8; i++)
#pragma unroll
        for (int j = 0; j < 8; j++) acc[i][j] = 0.0f;

    for (int k0 = 0; k0 < K; k0 += BK) {
        // -------- load A tile into As[k][m] --------
        if (!TA) {
            // A[M,K]: tile is 128 rows x 16 cols; transpose into smem
            const int row = tid >> 2;            // 0..63
            const int col = (tid & 3) * 4;       // 0,4,8,12
#pragma unroll
            for (int r = 0; r < BM; r += 64) {
                float4 v = *(const float4*)&A[(long long)(m0 + row + r) * K + (k0 + col)];
                As[col + 0][row + r] = v.x;
                As[col + 1][row + r] = v.y;
                As[col + 2][row + r] = v.z;
                As[col + 3][row + r] = v.w;
            }
        } else {
            // A[K,M]: tile is 16 rows x 128 cols; direct vector copy
            const int row = tid >> 5;            // 0..7
            const int col = (tid & 31) * 4;      // 0..124
#pragma unroll
            for (int r = 0; r < BK; r += 8) {
                float4 v = *(const float4*)&A[(long long)(k0 + row + r) * M + (m0 + col)];
                *(float4*)&As[row + r][col] = v;
            }
        }
        // -------- load B tile into Bs[k][n] --------
        if (!TB) {
            // B[K,N]: tile is 16 rows x 128 cols; direct vector copy
            const int row = tid >> 5;
            const int col = (tid & 31) * 4;
#pragma unroll
            for (int r = 0; r < BK; r += 8) {
                float4 v = *(const float4*)&B[(long long)(k0 + row + r) * N + (n0 + col)];
                *(float4*)&Bs[row + r][col] = v;
            }
        } else {
            // B[N,K]: tile is 128 rows (n) x 16 cols (k); transpose into smem
            const int row = tid >> 2;
            const int col = (tid & 3) * 4;
#pragma unroll
            for (int r = 0; r < BN; r += 64) {
                float4 v = *(const float4*)&B[(long long)(n0 + row + r) * K + (k0 + col)];
                Bs[col + 0][row + r] = v.x;
                Bs[col + 1][row + r] = v.y;
                Bs[col + 2][row + r] = v.z;
                Bs[col + 3][row + r] = v.w;
            }
        }
        __syncthreads();

        // -------- compute --------
#pragma unroll
        for (int k = 0; k < BK; k++) {
            float a[8], bb[8];
#pragma unroll
            for (int i = 0; i < 4; i++) {
                a[i]      = As[k][ty * 8 + i];
                a[i + 4]  = As[k][ty * 8 + 4 + i];
                bb[i]     = Bs[k][tx * 8 + i];
                bb[i + 4] = Bs[k][tx * 8 + 4 + i];
            }
#pragma unroll
            for (int i = 0; i < 8; i++)
#pragma unroll
                for (int j = 0; j < 8; j++)
                    acc[i][j] = fmaf(a[i], bb[j], acc[i][j]);
        }
        __syncthreads();
    }

    // -------- epilogue --------
#pragma unroll
    for (int i = 0; i < 8; i++) {
        const long long row = m0 + ty * 8 + i;
#pragma unroll
        for (int j = 0; j < 8; j += 4) {
            float4 v;
            v.x = acc[i][j + 0] * alpha;
            v.y = acc[i][j + 1] * alpha;
            v.z = acc[i][j + 2] * alpha;
            v.w = acc[i][j + 3] * alpha;
            *(float4*)&D[row * N + (n0 + tx * 8 + j)] = v;
        }
    }
}

extern "C" void kernel_launch(void* const* d_in, const int* in_sizes, int n_in,
                              void* d_out, int out_size)
{
    const float* x  = (const float*)d_in[0];   // [8, 4096, 1024]
    const float* Wt = (const float*)d_in[1];   // W_theta [256, 1024]
    const float* Wp = (const float*)d_in[2];   // W_phi   [256, 1024]
    const float* Wg = (const float*)d_in[3];   // W_g     [1024, 1024]
    float* out = (float*)d_out;                // [8, 4096, 1024]

    float* C; float* P; float* Q; float* R;
    cudaGetSymbolAddress((void**)&C, g_C);
    cudaGetSymbolAddress((void**)&P, g_P);
    cudaGetSymbolAddress((void**)&Q, g_Q);
    cudaGetSymbolAddress((void**)&R, g_R);

    const float scale = 1.0f / sqrtf((float)FDIM);  // 1/32

    const long long sX = (long long)NSEQ * FDIM;   // per-batch x stride
    const long long sC = (long long)FDIM * FDIM;
    const long long sP = (long long)LDIM * FDIM;
    const long long sR = (long long)FDIM * ODIM;

    // 1) C[b] = x[b]^T x[b]             M=N=1024, K=4096   (TA: x is [K,M])
    sgemm_kernel<true, false><<<dim3(FDIM / 128, FDIM / 128, BATCH), 256>>>(
        x, x, C, FDIM, FDIM, NSEQ, sX, sX, sC, 1.0f);

    // 2) P[b] = scale * W_phi @ C[b]    M=256, N=1024, K=1024
    sgemm_kernel<false, false><<<dim3(FDIM / 128, LDIM / 128, BATCH), 256>>>(
        Wp, C, P, LDIM, FDIM, FDIM, 0, sC, sP, scale);

    // 3) Q[b] = P[b] @ W_g^T            M=256, N=1024, K=1024  (TB: Wg is [N,K])
    sgemm_kernel<false, true><<<dim3(ODIM / 128, LDIM / 128, BATCH), 256>>>(
        P, Wg, Q, LDIM, ODIM, FDIM, sP, 0, sP, 1.0f);

    // 4) R[b] = W_theta^T @ Q[b]        M=1024, N=1024, K=256  (TA: Wt is [K,M])
    sgemm_kernel<true, false><<<dim3(ODIM / 128, FDIM / 128, BATCH), 256>>>(
        Wt, Q, R, FDIM, ODIM, LDIM, 0, sP, sR, 1.0f);

    // 5) out[b] = x[b] @ R[b]           M=4096, N=1024, K=1024
    sgemm_kernel<false, false><<<dim3(ODIM / 128, NSEQ / 128, BATCH), 256>>>(
        x, R, out, NSEQ, ODIM, FDIM, sX, sR, sX, 1.0f);
}

// round 3
// speedup vs baseline: 3.0080x; 3.0080x over previous
#include <cuda_runtime.h>
#include <cuda_bf16.h>
#include <math.h>
#include <stdint.h>

// ---------------- problem constants ----------------
#define BATCH 8
#define NSEQ  4096
#define FDIM  1024
#define LDIM  256
#define ODIM  1024

// ---------------- scratch (device globals) ----------------
__device__ __nv_bfloat16 g_xh [BATCH * NSEQ * FDIM];   // x hi      [B,S,F]
__device__ __nv_bfloat16 g_xl [BATCH * NSEQ * FDIM];   // x lo
__device__ __nv_bfloat16 g_xth[BATCH * FDIM * NSEQ];   // x^T hi    [B,F,S]
__device__ __nv_bfloat16 g_xtl[BATCH * FDIM * NSEQ];   // x^T lo
__device__ __nv_bfloat16 g_Ch [BATCH * FDIM * FDIM];   // C = x^T x [B,F,F] (symmetric)
__device__ __nv_bfloat16 g_Cl [BATCH * FDIM * FDIM];
__device__ __nv_bfloat16 g_Ph [BATCH * LDIM * FDIM];   // P = s*Wphi*C [B,L,F]
__device__ __nv_bfloat16 g_Pl [BATCH * LDIM * FDIM];
__device__ __nv_bfloat16 g_Qh [BATCH * ODIM * LDIM];   // QT [B,O,L]
__device__ __nv_bfloat16 g_Ql [BATCH * ODIM * LDIM];
__device__ __nv_bfloat16 g_Rh [BATCH * ODIM * FDIM];   // RT [B,O,F]
__device__ __nv_bfloat16 g_Rl [BATCH * ODIM * FDIM];
__device__ __nv_bfloat16 g_Wph[LDIM * FDIM];
__device__ __nv_bfloat16 g_Wpl[LDIM * FDIM];
__device__ __nv_bfloat16 g_Wgh[ODIM * FDIM];
__device__ __nv_bfloat16 g_Wgl[ODIM * FDIM];
__device__ __nv_bfloat16 g_Wth[FDIM * LDIM];           // Wtheta^T [F,L]
__device__ __nv_bfloat16 g_Wtl[FDIM * LDIM];

// ---------------- PTX helpers (compute_103-safe: no tcgen05) ----------------
__device__ __forceinline__ uint32_t smem_u32(const void* p) {
    uint32_t a;
    asm("{ .reg .u64 t; cvta.to.shared.u64 t, %1; cvt.u32.u64 %0, t; }" : "=r"(a) : "l"(p));
    return a;
}
__device__ __forceinline__ void cp16(uint32_t dst, const void* src) {
    asm volatile("cp.async.cg.shared.global [%0], [%1], 16;\n" :: "r"(dst), "l"(src));
}
#define CP_COMMIT()  asm volatile("cp.async.commit_group;\n" ::: "memory")
#define CP_WAIT0()   asm volatile("cp.async.wait_group 0;\n" ::: "memory")
#define CP_WAIT1()   asm volatile("cp.async.wait_group 1;\n" ::: "memory")
#define CP_WAIT2()   asm volatile("cp.async.wait_group 2;\n" ::: "memory")

__device__ __forceinline__ void ldsm4(uint32_t* r, uint32_t addr) {
    asm volatile("ldmatrix.sync.aligned.m8n8.x4.shared.b16 {%0,%1,%2,%3}, [%4];"
        : "=r"(r[0]), "=r"(r[1]), "=r"(r[2]), "=r"(r[3]) : "r"(addr));
}
__device__ __forceinline__ void mma16816(float* d, const uint32_t* a, const uint32_t* b) {
    asm volatile(
        "mma.sync.aligned.m16n8k16.row.col.f32.bf16.bf16.f32 "
        "{%0,%1,%2,%3}, {%4,%5,%6,%7}, {%8,%9}, {%0,%1,%2,%3};"
        : "+f"(d[0]), "+f"(d[1]), "+f"(d[2]), "+f"(d[3])
        : "r"(a[0]), "r"(a[1]), "r"(a[2]), "r"(a[3]), "r"(b[0]), "r"(b[1]));
}
__device__ __forceinline__ uint32_t sw128(uint32_t off) {
    return off ^ ((off >> 3) & 0x70);
}

// smem layout: 3 stages x 64KB. Each stage: Ah | Al | Bh | Bl (16KB each, 128 rows x 128B)
#define STAGE_BYTES 65536
#define OFF_AH 0
#define OFF_AL 16384
#define OFF_BH 32768
#define OFF_BL 49152
#define GEMM_SMEM (3 * STAGE_BYTES)

// ---------------- HMMA GEMM: D[m,n] = alpha * sum_k A[m,k]*B[n,k] (bf16x3, batched) ----------------
// A,B: (hi,lo) bf16 pairs, row-major [rows, K] (K-major). M,N mult of 128, K mult of 64.
// mode 0: fp32 out to Df;  mode 1: bf16 (hi,lo) out to Dh/Dl.
__global__ void __launch_bounds__(256, 1)
gemm_bf16x3(const __nv_bfloat16* __restrict__ Ah, const __nv_bfloat16* __restrict__ Al,
            const __nv_bfloat16* __restrict__ Bh, const __nv_bfloat16* __restrict__ Bl,
            float* __restrict__ Df, __nv_bfloat16* __restrict__ Dh, __nv_bfloat16* __restrict__ Dl,
            int N, int K,
            long long sA, long long sB, long long sD,
            float alpha, int mode)
{
    extern __shared__ char smem[];
    const int b = blockIdx.z;
    Ah += (long long)b * sA;  Al += (long long)b * sA;
    Bh += (long long)b * sB;  Bl += (long long)b * sB;

    const int m0 = blockIdx.y * 128;
    const int n0 = blockIdx.x * 128;
    const int tid = (int)threadIdx.x;
    const int wid = tid >> 5;
    const int lid = tid & 31;
    const int wm = (wid >> 2) * 64;   // warp M offset within block tile
    const int wn = (wid & 3) * 32;    // warp N offset

    const uint32_t sb = smem_u32(smem);
    const int nch = K >> 6;

    // ---- async loader: one K=64 chunk of Ah/Al/Bh/Bl into given stage ----
    auto load_chunk = [&](int kc, int stage) {
        const long long kofs = (long long)kc * 64;
        const uint32_t sbase = sb + stage * STAGE_BYTES;
#pragma unroll
        for (int j = 0; j < 4; j++) {
            int idx = j * 256 + tid;                 // 0..1023
            int r   = idx >> 3;                      // row 0..127
            int cb  = (idx & 7) << 4;                // byte col 0..112
            uint32_t sw = sw128((uint32_t)(r * 128 + cb));
            long long ea = (long long)(m0 + r) * K + kofs + (cb >> 1);
            long long eb = (long long)(n0 + r) * K + kofs + (cb >> 1);
            cp16(sbase + OFF_AH + sw, Ah + ea);
            cp16(sbase + OFF_AL + sw, Al + ea);
            cp16(sbase + OFF_BH + sw, Bh + eb);
            cp16(sbase + OFF_BL + sw, Bl + eb);
        }
        CP_COMMIT();
    };

    float acc[4][4][4];
#pragma unroll
    for (int i = 0; i < 4; i++)
#pragma unroll
        for (int j = 0; j < 4; j++)
#pragma unroll
            for (int c = 0; c < 4; c++) acc[i][j][c] = 0.0f;

    // ldmatrix per-lane logical coordinates
    const int a_row = wm + (lid & 15);           // + mt*16
    const int a_cb  = (lid >> 4) * 16;           // + k16*32  (bytes)
    const int b_row = wn + (lid & 7) + ((lid >> 4) & 1) * 8;   // + np*16
    const int b_cb  = ((lid >> 3) & 1) * 16;     // + k16*32  (bytes)

    // ---- prologue ----
    load_chunk(0, 0);
    if (nch > 1) load_chunk(1, 1);
    if (nch > 2) load_chunk(2, 2);

    for (int i = 0; i < nch; i++) {
        const int s = i % 3;
        const int rem = nch - 1 - i;
        if (rem >= 2)      { CP_WAIT2(); }
        else if (rem == 1) { CP_WAIT1(); }
        else               { CP_WAIT0(); }
        __syncthreads();

        const uint32_t sbase = sb + s * STAGE_BYTES;
#pragma unroll
        for (int k16 = 0; k16 < 4; k16++) {
            const int kb = k16 * 32;
            uint32_t ah[4][4], al[4][4], bh[2][4], bl[2][4];
#pragma unroll
            for (int mt = 0; mt < 4; mt++) {
                uint32_t off = (uint32_t)((a_row + mt * 16) * 128 + kb + a_cb);
                uint32_t sw = sw128(off);
                ldsm4(ah[mt], sbase + OFF_AH + sw);
                ldsm4(al[mt], sbase + OFF_AL + sw);
            }
#pragma unroll
            for (int np = 0; np < 2; np++) {
                uint32_t off = (uint32_t)((b_row + np * 16) * 128 + kb + b_cb);
                uint32_t sw = sw128(off);
                ldsm4(bh[np], sbase + OFF_BH + sw);
                ldsm4(bl[np], sbase + OFF_BL + sw);
            }
#pragma unroll
            for (int mt = 0; mt < 4; mt++) {
#pragma unroll
                for (int nt = 0; nt < 4; nt++) {
                    const uint32_t* bhf = &bh[nt >> 1][(nt & 1) * 2];
                    const uint32_t* blf = &bl[nt >> 1][(nt & 1) * 2];
                    mma16816(acc[mt][nt], ah[mt], bhf);   // hi*hi
                    mma16816(acc[mt][nt], ah[mt], blf);   // hi*lo
                    mma16816(acc[mt][nt], al[mt], bhf);   // lo*hi
                }
            }
        }
        __syncthreads();
        if (i + 3 < nch) load_chunk(i + 3, s);
    }

    // ---- epilogue ----
    const int er = lid >> 2;          // 0..7
    const int ec = (lid & 3) * 2;     // 0,2,4,6
#pragma unroll
    for (int mt = 0; mt < 4; mt++) {
#pragma unroll
        for (int nt = 0; nt < 4; nt++) {
            const long long row0 = m0 + wm + mt * 16 + er;
            const long long col  = n0 + wn + nt * 8 + ec;
            if (mode == 0) {
                float2 v0, v1;
                v0.x = acc[mt][nt][0] * alpha; v0.y = acc[mt][nt][1] * alpha;
                v1.x = acc[mt][nt][2] * alpha; v1.y = acc[mt][nt][3] * alpha;
                *(float2*)(Df + (long long)b * sD + row0 * N + col)       = v0;
                *(float2*)(Df + (long long)b * sD + (row0 + 8) * N + col) = v1;
            } else {
                float p0 = acc[mt][nt][0] * alpha, p1 = acc[mt][nt][1] * alpha;
                float p2 = acc[mt][nt][2] * alpha, p3 = acc[mt][nt][3] * alpha;
                __nv_bfloat16 h0 = __float2bfloat16(p0), h1 = __float2bfloat16(p1);
                __nv_bfloat16 h2 = __float2bfloat16(p2), h3 = __float2bfloat16(p3);
                __nv_bfloat16 l0 = __float2bfloat16(p0 - __bfloat162float(h0));
                __nv_bfloat16 l1 = __float2bfloat16(p1 - __bfloat162float(h1));
                __nv_bfloat16 l2 = __float2bfloat16(p2 - __bfloat162float(h2));
                __nv_bfloat16 l3 = __float2bfloat16(p3 - __bfloat162float(h3));
                long long base = (long long)b * sD;
                *(__nv_bfloat162*)(Dh + base + row0 * N + col)       = __nv_bfloat162(h0, h1);
                *(__nv_bfloat162*)(Dh + base + (row0 + 8) * N + col) = __nv_bfloat162(h2, h3);
                *(__nv_bfloat162*)(Dl + base + row0 * N + col)       = __nv_bfloat162(l0, l1);
                *(__nv_bfloat162*)(Dl + base + (row0 + 8) * N + col) = __nv_bfloat162(l2, l3);
            }
        }
    }
}

// ---------------- conversion kernels ----------------
__device__ __forceinline__ void split_bf16(float v, __nv_bfloat16& h, __nv_bfloat16& l) {
    h = __float2bfloat16(v);
    l = __float2bfloat16(v - __bfloat162float(h));
}

// x [B,S,F] fp32 -> x hi/lo [B,S,F] and xT hi/lo [B,F,S]
__global__ void conv_x_kernel(const float* __restrict__ x,
                              __nv_bfloat16* __restrict__ xh, __nv_bfloat16* __restrict__ xl,
                              __nv_bfloat16* __restrict__ xth, __nv_bfloat16* __restrict__ xtl)
{
    __shared__ float t[32][33];
    const int b = blockIdx.z;
    const int s0 = blockIdx.x * 32;
    const int f0 = blockIdx.y * 32;
    const long long bo  = (long long)b * NSEQ * FDIM;
    const long long bot = (long long)b * FDIM * NSEQ;
    const int tx = threadIdx.x, ty = threadIdx.y;

#pragma unroll
    for (int r = 0; r < 4; r++) {
        int srow = s0 + ty + r * 8;
        float v = x[bo + (long long)srow * FDIM + f0 + tx];
        t[ty + r * 8][tx] = v;
        __nv_bfloat16 h, l; split_bf16(v, h, l);
        xh[bo + (long long)srow * FDIM + f0 + tx] = h;
        xl[bo + (long long)srow * FDIM + f0 + tx] = l;
    }
    __syncthreads();
#pragma unroll
    for (int r = 0; r < 4; r++) {
        int frow = f0 + ty + r * 8;
        float v = t[tx][ty + r * 8];
        __nv_bfloat16 h, l; split_bf16(v, h, l);
        xth[bot + (long long)frow * NSEQ + s0 + tx] = h;
        xtl[bot + (long long)frow * NSEQ + s0 + tx] = l;
    }
}

// plain fp32 -> bf16 hi/lo
__global__ void conv_pair_kernel(const float* __restrict__ in,
                                 __nv_bfloat16* __restrict__ oh, __nv_bfloat16* __restrict__ ol, int n)
{
    int i = blockIdx.x * blockDim.x + threadIdx.x;
    if (i < n) {
        __nv_bfloat16 h, l; split_bf16(in[i], h, l);
        oh[i] = h; ol[i] = l;
    }
}

// transpose+convert: in [R,C] fp32 -> out [C,R] bf16 hi/lo
__global__ void conv_T_kernel(const float* __restrict__ in,
                              __nv_bfloat16* __restrict__ oh, __nv_bfloat16* __restrict__ ol,
                              int R, int C)
{
    __shared__ float t[32][33];
    const int r0 = blockIdx.y * 32;
    const int c0 = blockIdx.x * 32;
    const int tx = threadIdx.x, ty = threadIdx.y;
#pragma unroll
    for (int r = 0; r < 4; r++)
        t[ty + r * 8][tx] = in[(long long)(r0 + ty + r * 8) * C + c0 + tx];
    __syncthreads();
#pragma unroll
    for (int r = 0; r < 4; r++) {
        float v = t[tx][ty + r * 8];
        __nv_bfloat16 h, l; split_bf16(v, h, l);
        oh[(long long)(c0 + ty + r * 8) * R + r0 + tx] = h;
        ol[(long long)(c0 + ty + r * 8) * R + r0 + tx] = l;
    }
}

// ---------------- launcher ----------------
extern "C" void kernel_launch(void* const* d_in, const int* in_sizes, int n_in,
                              void* d_out, int out_size)
{
    const float* x  = (const float*)d_in[0];   // [8,4096,1024]
    const float* Wt = (const float*)d_in[1];   // [256,1024]
    const float* Wp = (const float*)d_in[2];   // [256,1024]
    const float* Wg = (const float*)d_in[3];   // [1024,1024]
    float* out = (float*)d_out;                // [8,4096,1024]

    __nv_bfloat16 *xh, *xl, *xth, *xtl, *Ch, *Cl, *Ph, *Pl, *Qh, *Ql, *Rh, *Rl;
    __nv_bfloat16 *Wph, *Wpl, *Wgh, *Wgl, *Wth, *Wtl;
    cudaGetSymbolAddress((void**)&xh, g_xh);   cudaGetSymbolAddress((void**)&xl, g_xl);
    cudaGetSymbolAddress((void**)&xth, g_xth); cudaGetSymbolAddress((void**)&xtl, g_xtl);
    cudaGetSymbolAddress((void**)&Ch, g_Ch);   cudaGetSymbolAddress((void**)&Cl, g_Cl);
    cudaGetSymbolAddress((void**)&Ph, g_Ph);   cudaGetSymbolAddress((void**)&Pl, g_Pl);
    cudaGetSymbolAddress((void**)&Qh, g_Qh);   cudaGetSymbolAddress((void**)&Ql, g_Ql);
    cudaGetSymbolAddress((void**)&Rh, g_Rh);   cudaGetSymbolAddress((void**)&Rl, g_Rl);
    cudaGetSymbolAddress((void**)&Wph, g_Wph); cudaGetSymbolAddress((void**)&Wpl, g_Wpl);
    cudaGetSymbolAddress((void**)&Wgh, g_Wgh); cudaGetSymbolAddress((void**)&Wgl, g_Wgl);
    cudaGetSymbolAddress((void**)&Wth, g_Wth); cudaGetSymbolAddress((void**)&Wtl, g_Wtl);

    cudaFuncSetAttribute(gemm_bf16x3, cudaFuncAttributeMaxDynamicSharedMemorySize, GEMM_SMEM);

    const float scale = 1.0f / 32.0f;  // 1/sqrt(1024)

    // conversions
    conv_x_kernel<<<dim3(NSEQ / 32, FDIM / 32, BATCH), dim3(32, 8)>>>(x, xh, xl, xth, xtl);
    conv_pair_kernel<<<(LDIM * FDIM) / 256, 256>>>(Wp, Wph, Wpl, LDIM * FDIM);
    conv_pair_kernel<<<(ODIM * FDIM) / 256, 256>>>(Wg, Wgh, Wgl, ODIM * FDIM);
    conv_T_kernel<<<dim3(FDIM / 32, LDIM / 32), dim3(32, 8)>>>(Wt, Wth, Wtl, LDIM, FDIM);

    const long long sX  = (long long)NSEQ * FDIM;
    const long long sXT = (long long)FDIM * NSEQ;
    const long long sC  = (long long)FDIM * FDIM;
    const long long sP  = (long long)LDIM * FDIM;
    const long long sQ  = (long long)ODIM * LDIM;
    const long long sR  = (long long)ODIM * FDIM;

    // 1) C[f1,f2] = sum_s xT[f1,s]*xT[f2,s]    M=1024,N=1024,K=4096
    gemm_bf16x3<<<dim3(8, 8, BATCH), 256, GEMM_SMEM>>>(
        xth, xtl, xth, xtl, nullptr, Ch, Cl, FDIM, NSEQ, sXT, sXT, sC, 1.0f, 1);

    // 2) P[l,f2] = scale*sum_f1 Wphi[l,f1]*C[f2,f1]  (C symmetric)  M=256,N=1024,K=1024
    gemm_bf16x3<<<dim3(8, 2, BATCH), 256, GEMM_SMEM>>>(
        Wph, Wpl, Ch, Cl, nullptr, Ph, Pl, FDIM, FDIM, 0, sC, sP, scale, 1);

    // 3) QT[o,l] = sum_f Wg[o,f]*P[l,f]        M=1024,N=256,K=1024
    gemm_bf16x3<<<dim3(2, 8, BATCH), 256, GEMM_SMEM>>>(
        Wgh, Wgl, Ph, Pl, nullptr, Qh, Ql, LDIM, FDIM, 0, sP, sQ, 1.0f, 1);

    // 4) RT[o,f] = sum_l QT[o,l]*WthetaT[f,l]  M=1024,N=1024,K=256
    gemm_bf16x3<<<dim3(8, 8, BATCH), 256, GEMM_SMEM>>>(
        Qh, Ql, Wth, Wtl, nullptr, Rh, Rl, FDIM, LDIM, sQ, 0, sR, 1.0f, 1);

    // 5) out[s,o] = sum_f x[s,f]*RT[o,f]       M=4096,N=1024,K=1024
    gemm_bf16x3<<<dim3(8, 32, BATCH), 256, GEMM_SMEM>>>(
        xh, xl, Rh, Rl, out, nullptr, nullptr, ODIM, FDIM, sX, sR, sX, 1.0f, 0);
}

// round 4
// speedup vs baseline: 3.8985x; 1.2961x over previous
#include <cuda_runtime.h>
#include <cuda_bf16.h>
#include <math.h>
#include <stdint.h>

// ---------------- problem constants ----------------
#define BATCH 8
#define NSEQ  4096
#define FDIM  1024
#define LDIM  256
#define ODIM  1024

// ---------------- scratch (device globals) ----------------
__device__ __nv_bfloat16 g_xh [BATCH * NSEQ * FDIM];   // x hi [B,S,F]
__device__ __nv_bfloat16 g_xl [BATCH * NSEQ * FDIM];   // x lo
__device__ __nv_bfloat16 g_Ch [BATCH * FDIM * FDIM];   // C = x^T x (symmetric)
__device__ __nv_bfloat16 g_Cl [BATCH * FDIM * FDIM];
__device__ __nv_bfloat16 g_Ph [BATCH * LDIM * FDIM];   // P = s*Wphi*C
__device__ __nv_bfloat16 g_Pl [BATCH * LDIM * FDIM];
__device__ __nv_bfloat16 g_Qh [BATCH * ODIM * LDIM];   // QT
__device__ __nv_bfloat16 g_Ql [BATCH * ODIM * LDIM];
__device__ __nv_bfloat16 g_Rh [BATCH * ODIM * FDIM];   // RT
__device__ __nv_bfloat16 g_Rl [BATCH * ODIM * FDIM];
__device__ __nv_bfloat16 g_Wph[LDIM * FDIM];
__device__ __nv_bfloat16 g_Wpl[LDIM * FDIM];
__device__ __nv_bfloat16 g_Wgh[ODIM * FDIM];
__device__ __nv_bfloat16 g_Wgl[ODIM * FDIM];
__device__ __nv_bfloat16 g_Wth[FDIM * LDIM];           // Wtheta^T [F,L]
__device__ __nv_bfloat16 g_Wtl[FDIM * LDIM];

// ---------------- PTX helpers ----------------
__device__ __forceinline__ uint32_t smem_u32(const void* p) {
    uint32_t a;
    asm("{ .reg .u64 t; cvta.to.shared.u64 t, %1; cvt.u32.u64 %0, t; }" : "=r"(a) : "l"(p));
    return a;
}
__device__ __forceinline__ void cp16(uint32_t dst, const void* src) {
    asm volatile("cp.async.cg.shared.global [%0], [%1], 16;\n" :: "r"(dst), "l"(src));
}
#define CP_COMMIT()  asm volatile("cp.async.commit_group;\n" ::: "memory")
#define CP_WAIT0()   asm volatile("cp.async.wait_group 0;\n" ::: "memory")
#define CP_WAIT1()   asm volatile("cp.async.wait_group 1;\n" ::: "memory")
#define CP_WAIT2()   asm volatile("cp.async.wait_group 2;\n" ::: "memory")

__device__ __forceinline__ void ldsm4(uint32_t* r, uint32_t addr) {
    asm volatile("ldmatrix.sync.aligned.m8n8.x4.shared.b16 {%0,%1,%2,%3}, [%4];"
        : "=r"(r[0]), "=r"(r[1]), "=r"(r[2]), "=r"(r[3]) : "r"(addr));
}
__device__ __forceinline__ void ldsm4t(uint32_t* r, uint32_t addr) {
    asm volatile("ldmatrix.sync.aligned.m8n8.x4.trans.shared.b16 {%0,%1,%2,%3}, [%4];"
        : "=r"(r[0]), "=r"(r[1]), "=r"(r[2]), "=r"(r[3]) : "r"(addr));
}
__device__ __forceinline__ void mma16816(float* d, const uint32_t* a, const uint32_t* b) {
    asm volatile(
        "mma.sync.aligned.m16n8k16.row.col.f32.bf16.bf16.f32 "
        "{%0,%1,%2,%3}, {%4,%5,%6,%7}, {%8,%9}, {%0,%1,%2,%3};"
        : "+f"(d[0]), "+f"(d[1]), "+f"(d[2]), "+f"(d[3])
        : "r"(a[0]), "r"(a[1]), "r"(a[2]), "r"(a[3]), "r"(b[0]), "r"(b[1]));
}
__device__ __forceinline__ uint32_t sw128(uint32_t off) {
    return off ^ ((off >> 3) & 0x70);
}
__device__ __forceinline__ void split_bf16(float v, __nv_bfloat16& h, __nv_bfloat16& l) {
    h = __float2bfloat16(v);
    l = __float2bfloat16(v - __bfloat162float(h));
}

// smem: 3 stages x 64KB. Stage: Ah | Al | Bh | Bl (16KB each)
#define STAGE_BYTES 65536
#define OFF_AH 0
#define OFF_AL 16384
#define OFF_BH 32768
#define OFF_BL 49152
#define GEMM_SMEM (3 * STAGE_BYTES)

// ============================================================================
// Generic HMMA GEMM: D[m,n] = alpha * sum_k A[m,k]*B[n,k]  (bf16x3, batched)
// A,B K-major [rows,K]. mode 0: fp32 out; mode 1: bf16 hi/lo out.
// ============================================================================
__global__ void __launch_bounds__(256, 1)
gemm_bf16x3(const __nv_bfloat16* __restrict__ Ah, const __nv_bfloat16* __restrict__ Al,
            const __nv_bfloat16* __restrict__ Bh, const __nv_bfloat16* __restrict__ Bl,
            float* __restrict__ Df, __nv_bfloat16* __restrict__ Dh, __nv_bfloat16* __restrict__ Dl,
            int N, int K,
            long long sA, long long sB, long long sD,
            float alpha, int mode)
{
    extern __shared__ char smem[];
    const int b = blockIdx.z;
    Ah += (long long)b * sA;  Al += (long long)b * sA;
    Bh += (long long)b * sB;  Bl += (long long)b * sB;

    const int m0 = blockIdx.y * 128;
    const int n0 = blockIdx.x * 128;
    const int tid = (int)threadIdx.x;
    const int wid = tid >> 5;
    const int lid = tid & 31;
    const int wm = (wid >> 2) * 64;
    const int wn = (wid & 3) * 32;

    const uint32_t sb = smem_u32(smem);
    const int nch = K >> 6;

    auto load_chunk = [&](int kc, int stage) {
        const long long kofs = (long long)kc * 64;
        const uint32_t sbase = sb + stage * STAGE_BYTES;
#pragma unroll
        for (int j = 0; j < 4; j++) {
            int idx = j * 256 + tid;
            int r   = idx >> 3;
            int cb  = (idx & 7) << 4;
            uint32_t sw = sw128((uint32_t)(r * 128 + cb));
            long long ea = (long long)(m0 + r) * K + kofs + (cb >> 1);
            long long eb = (long long)(n0 + r) * K + kofs + (cb >> 1);
            cp16(sbase + OFF_AH + sw, Ah + ea);
            cp16(sbase + OFF_AL + sw, Al + ea);
            cp16(sbase + OFF_BH + sw, Bh + eb);
            cp16(sbase + OFF_BL + sw, Bl + eb);
        }
        CP_COMMIT();
    };

    float acc[4][4][4];
#pragma unroll
    for (int i = 0; i < 4; i++)
#pragma unroll
        for (int j = 0; j < 4; j++)
#pragma unroll
            for (int c = 0; c < 4; c++) acc[i][j][c] = 0.0f;

    const int a_row = wm + (lid & 15);
    const int a_cb  = (lid >> 4) * 16;
    const int b_row = wn + (lid & 7) + ((lid >> 4) & 1) * 8;
    const int b_cb  = ((lid >> 3) & 1) * 16;

    load_chunk(0, 0);
    if (nch > 1) load_chunk(1, 1);
    if (nch > 2) load_chunk(2, 2);

    for (int i = 0; i < nch; i++) {
        const int s = i % 3;
        const int rem = nch - 1 - i;
        if (rem >= 2)      { CP_WAIT2(); }
        else if (rem == 1) { CP_WAIT1(); }
        else               { CP_WAIT0(); }
        __syncthreads();

        const uint32_t sbase = sb + s * STAGE_BYTES;
#pragma unroll
        for (int k16 = 0; k16 < 4; k16++) {
            const int kb = k16 * 32;
            uint32_t ah[4][4], al[4][4], bh[2][4], bl[2][4];
#pragma unroll
            for (int mt = 0; mt < 4; mt++) {
                uint32_t sw = sw128((uint32_t)((a_row + mt * 16) * 128 + kb + a_cb));
                ldsm4(ah[mt], sbase + OFF_AH + sw);
                ldsm4(al[mt], sbase + OFF_AL + sw);
            }
#pragma unroll
            for (int np = 0; np < 2; np++) {
                uint32_t sw = sw128((uint32_t)((b_row + np * 16) * 128 + kb + b_cb));
                ldsm4(bh[np], sbase + OFF_BH + sw);
                ldsm4(bl[np], sbase + OFF_BL + sw);
            }
#pragma unroll
            for (int mt = 0; mt < 4; mt++) {
#pragma unroll
                for (int nt = 0; nt < 4; nt++) {
                    const uint32_t* bhf = &bh[nt >> 1][(nt & 1) * 2];
                    const uint32_t* blf = &bl[nt >> 1][(nt & 1) * 2];
                    mma16816(acc[mt][nt], ah[mt], bhf);
                    mma16816(acc[mt][nt], ah[mt], blf);
                    mma16816(acc[mt][nt], al[mt], bhf);
                }
            }
        }
        __syncthreads();
        if (i + 3 < nch) load_chunk(i + 3, s);
    }

    const int er = lid >> 2;
    const int ec = (lid & 3) * 2;
#pragma unroll
    for (int mt = 0; mt < 4; mt++) {
#pragma unroll
        for (int nt = 0; nt < 4; nt++) {
            const long long row0 = m0 + wm + mt * 16 + er;
            const long long col  = n0 + wn + nt * 8 + ec;
            if (mode == 0) {
                float2 v0, v1;
                v0.x = acc[mt][nt][0] * alpha; v0.y = acc[mt][nt][1] * alpha;
                v1.x = acc[mt][nt][2] * alpha; v1.y = acc[mt][nt][3] * alpha;
                *(float2*)(Df + (long long)b * sD + row0 * N + col)       = v0;
                *(float2*)(Df + (long long)b * sD + (row0 + 8) * N + col) = v1;
            } else {
                float p0 = acc[mt][nt][0] * alpha, p1 = acc[mt][nt][1] * alpha;
                float p2 = acc[mt][nt][2] * alpha, p3 = acc[mt][nt][3] * alpha;
                __nv_bfloat16 h0, h1, h2, h3, l0, l1, l2, l3;
                split_bf16(p0, h0, l0); split_bf16(p1, h1, l1);
                split_bf16(p2, h2, l2); split_bf16(p3, h3, l3);
                long long base = (long long)b * sD;
                *(__nv_bfloat162*)(Dh + base + row0 * N + col)       = __nv_bfloat162(h0, h1);
                *(__nv_bfloat162*)(Dh + base + (row0 + 8) * N + col) = __nv_bfloat162(h2, h3);
                *(__nv_bfloat162*)(Dl + base + row0 * N + col)       = __nv_bfloat162(l0, l1);
                *(__nv_bfloat162*)(Dl + base + (row0 + 8) * N + col) = __nv_bfloat162(l2, l3);
            }
        }
    }
}

// ============================================================================
// SYRK: C[f1,f2] = sum_s x[s,f1]*x[s,f2], upper-triangle blocks only.
// x stored [S,F]; smem tiles are [64 k-rows][128 cols] (256B rows), fragments
// via ldmatrix.trans. bf16x3, bf16 hi/lo epilogue.
// ============================================================================
__global__ void __launch_bounds__(256, 1)
syrk_bf16x3(const __nv_bfloat16* __restrict__ xh, const __nv_bfloat16* __restrict__ xl,
            __nv_bfloat16* __restrict__ Ch, __nv_bfloat16* __restrict__ Cl)
{
    extern __shared__ char smem[];
    // map blockIdx.x (0..35) -> (by, bx) with bx >= by
    int t = blockIdx.x, by = 0;
    while (t >= 8 - by) { t -= 8 - by; by++; }
    const int bx = by + t;
    const bool diag = (bx == by);

    const int b = blockIdx.z;
    const long long xoff = (long long)b * NSEQ * FDIM;
    const int m0 = by * 128, n0 = bx * 128;
    const int tid = (int)threadIdx.x;
    const int wid = tid >> 5;
    const int lid = tid & 31;
    const int wm = (wid >> 2) * 64;
    const int wn = (wid & 3) * 32;

    const uint32_t sb = smem_u32(smem);
    const uint32_t offBH = diag ? OFF_AH : OFF_BH;   // alias B to A on diagonal
    const uint32_t offBL = offBH + 16384;

    auto load_chunk = [&](int kc, int stage) {
        const uint32_t sbase = sb + stage * STAGE_BYTES;
        const long long s0 = (long long)kc * 64;
#pragma unroll
        for (int j = 0; j < 4; j++) {
            int idx = j * 256 + tid;
            int r   = idx >> 4;            // k-row 0..63
            int cb  = (idx & 15) << 4;     // byte col 0..240
            uint32_t sw = (uint32_t)(r * 256 + cb) ^ (uint32_t)((r & 7) << 4);
            long long g = xoff + (s0 + r) * FDIM;
            cp16(sbase + OFF_AH + sw, xh + g + m0 + (cb >> 1));
            cp16(sbase + OFF_AL + sw, xl + g + m0 + (cb >> 1));
            if (!diag) {
                cp16(sbase + OFF_BH + sw, xh + g + n0 + (cb >> 1));
                cp16(sbase + OFF_BL + sw, xl + g + n0 + (cb >> 1));
            }
        }
        CP_COMMIT();
    };

    float acc[4][4][4];
#pragma unroll
    for (int i = 0; i < 4; i++)
#pragma unroll
        for (int j = 0; j < 4; j++)
#pragma unroll
            for (int c = 0; c < 4; c++) acc[i][j][c] = 0.0f;

    // trans-ldmatrix lane maps (fragments from [k][col] storage)
    const int a_krow  = ((lid >> 4) & 1) * 8 + (lid & 7);
    const int a_mbyte = ((lid >> 3) & 1) * 16;
    const int b_krow  = ((lid >> 3) & 1) * 8 + (lid & 7);
    const int b_nbyte = ((lid >> 4) & 1) * 16;

    const int nch = NSEQ >> 6;   // 64
    load_chunk(0, 0);
    load_chunk(1, 1);
    load_chunk(2, 2);

    for (int i = 0; i < nch; i++) {
        const int s = i % 3;
        const int rem = nch - 1 - i;
        if (rem >= 2)      { CP_WAIT2(); }
        else if (rem == 1) { CP_WAIT1(); }
        else               { CP_WAIT0(); }
        __syncthreads();

        const uint32_t sbase = sb + s * STAGE_BYTES;
#pragma unroll
        for (int k16 = 0; k16 < 4; k16++) {
            uint32_t ah[4][4], al[4][4], bh[2][4], bl[2][4];
#pragma unroll
            for (int mt = 0; mt < 4; mt++) {
                uint32_t off = (uint32_t)((k16 * 16 + a_krow) * 256 + (wm + mt * 16) * 2 + a_mbyte);
                off ^= (uint32_t)((a_krow & 7) << 4);
                ldsm4t(ah[mt], sbase + OFF_AH + off);
                ldsm4t(al[mt], sbase + OFF_AL + off);
            }
#pragma unroll
            for (int np = 0; np < 2; np++) {
                uint32_t off = (uint32_t)((k16 * 16 + b_krow) * 256 + (wn + np * 16) * 2 + b_nbyte);
                off ^= (uint32_t)((b_krow & 7) << 4);
                ldsm4t(bh[np], sbase + offBH + off);
                ldsm4t(bl[np], sbase + offBL + off);
            }
#pragma unroll
            for (int mt = 0; mt < 4; mt++) {
#pragma unroll
                for (int nt = 0; nt < 4; nt++) {
                    const uint32_t* bhf = &bh[nt >> 1][(nt & 1) * 2];
                    const uint32_t* blf = &bl[nt >> 1][(nt & 1) * 2];
                    mma16816(acc[mt][nt], ah[mt], bhf);
                    mma16816(acc[mt][nt], ah[mt], blf);
                    mma16816(acc[mt][nt], al[mt], bhf);
                }
            }
        }
        __syncthreads();
        if (i + 3 < nch) load_chunk(i + 3, s);
    }

    const int er = lid >> 2;
    const int ec = (lid & 3) * 2;
    const long long base = (long long)b * FDIM * FDIM;
#pragma unroll
    for (int mt = 0; mt < 4; mt++) {
#pragma unroll
        for (int nt = 0; nt < 4; nt++) {
            const long long row0 = m0 + wm + mt * 16 + er;
            const long long col  = n0 + wn + nt * 8 + ec;
            float p0 = acc[mt][nt][0], p1 = acc[mt][nt][1];
            float p2 = acc[mt][nt][2], p3 = acc[mt][nt][3];
            __nv_bfloat16 h0, h1, h2, h3, l0, l1, l2, l3;
            split_bf16(p0, h0, l0); split_bf16(p1, h1, l1);
            split_bf16(p2, h2, l2); split_bf16(p3, h3, l3);
            *(__nv_bfloat162*)(Ch + base + row0 * FDIM + col)       = __nv_bfloat162(h0, h1);
            *(__nv_bfloat162*)(Ch + base + (row0 + 8) * FDIM + col) = __nv_bfloat162(h2, h3);
            *(__nv_bfloat162*)(Cl + base + row0 * FDIM + col)       = __nv_bfloat162(l0, l1);
            *(__nv_bfloat162*)(Cl + base + (row0 + 8) * FDIM + col) = __nv_bfloat162(l2, l3);
        }
    }
}

// ============================================================================
// Mirror the upper triangle of C into the lower triangle (hi and lo).
// ============================================================================
__global__ void mirror_kernel(__nv_bfloat16* __restrict__ Ch, __nv_bfloat16* __restrict__ Cl)
{
    // blockIdx.x in 0..527 -> (ty, tx) 32x32 tiles with tx >= ty
    int t = blockIdx.x, ty = 0;
    while (t >= 32 - ty) { t -= 32 - ty; ty++; }
    const int tx = ty + t;
    const int b = blockIdx.y;
    const long long base = (long long)b * FDIM * FDIM;
    __shared__ __nv_bfloat16 sh[32][33];
    __shared__ __nv_bfloat16 sl[32][33];
    const int x_ = threadIdx.x, y = threadIdx.y;   // 32 x 8
    const int r0 = ty * 32, c0 = tx * 32;
#pragma unroll
    for (int r = 0; r < 4; r++) {
        int i = r0 + y + r * 8;
        sh[y + r * 8][x_] = Ch[base + (long long)i * FDIM + c0 + x_];
        sl[y + r * 8][x_] = Cl[base + (long long)i * FDIM + c0 + x_];
    }
    __syncthreads();
#pragma unroll
    for (int r = 0; r < 4; r++) {
        int j = c0 + y + r * 8;   // target row
        int i = r0 + x_;          // target col
        if (j > i) {
            Ch[base + (long long)j * FDIM + i] = sh[x_][y + r * 8];
            Cl[base + (long long)j * FDIM + i] = sl[x_][y + r * 8];
        }
    }
}

// ---------------- conversion kernels ----------------
// elementwise x fp32 -> bf16 hi/lo (8 elems per thread)
__global__ void conv_x_kernel(const float4* __restrict__ x,
                              __nv_bfloat162* __restrict__ xh2, __nv_bfloat162* __restrict__ xl2)
{
    const int i = blockIdx.x * blockDim.x + threadIdx.x;
#pragma unroll
    for (int p = 0; p < 2; p++) {
        float4 v = x[i * 2 + p];
        __nv_bfloat16 h0, h1, h2, h3, l0, l1, l2, l3;
        split_bf16(v.x, h0, l0); split_bf16(v.y, h1, l1);
        split_bf16(v.z, h2, l2); split_bf16(v.w, h3, l3);
        xh2[i * 4 + p * 2 + 0] = __nv_bfloat162(h0, h1);
        xh2[i * 4 + p * 2 + 1] = __nv_bfloat162(h2, h3);
        xl2[i * 4 + p * 2 + 0] = __nv_bfloat162(l0, l1);
        xl2[i * 4 + p * 2 + 1] = __nv_bfloat162(l2, l3);
    }
}

__global__ void conv_pair_kernel(const float* __restrict__ in,
                                 __nv_bfloat16* __restrict__ oh, __nv_bfloat16* __restrict__ ol, int n)
{
    int i = blockIdx.x * blockDim.x + threadIdx.x;
    if (i < n) {
        __nv_bfloat16 h, l; split_bf16(in[i], h, l);
        oh[i] = h; ol[i] = l;
    }
}

__global__ void conv_T_kernel(const float* __restrict__ in,
                              __nv_bfloat16* __restrict__ oh, __nv_bfloat16* __restrict__ ol,
                              int R, int C)
{
    __shared__ float t[32][33];
    const int r0 = blockIdx.y * 32;
    const int c0 = blockIdx.x * 32;
    const int tx = threadIdx.x, ty = threadIdx.y;
#pragma unroll
    for (int r = 0; r < 4; r++)
        t[ty + r * 8][tx] = in[(long long)(r0 + ty + r * 8) * C + c0 + tx];
    __syncthreads();
#pragma unroll
    for (int r = 0; r < 4; r++) {
        float v = t[tx][ty + r * 8];
        __nv_bfloat16 h, l; split_bf16(v, h, l);
        oh[(long long)(c0 + ty + r * 8) * R + r0 + tx] = h;
        ol[(long long)(c0 + ty + r * 8) * R + r0 + tx] = l;
    }
}

// ---------------- launcher ----------------
extern "C" void kernel_launch(void* const* d_in, const int* in_sizes, int n_in,
                              void* d_out, int out_size)
{
    const float* x  = (const float*)d_in[0];   // [8,4096,1024]
    const float* Wt = (const float*)d_in[1];   // [256,1024]
    const float* Wp = (const float*)d_in[2];   // [256,1024]
    const float* Wg = (const float*)d_in[3];   // [1024,1024]
    float* out = (float*)d_out;                // [8,4096,1024]

    __nv_bfloat16 *xh, *xl, *Ch, *Cl, *Ph, *Pl, *Qh, *Ql, *Rh, *Rl;
    __nv_bfloat16 *Wph, *Wpl, *Wgh, *Wgl, *Wth, *Wtl;
    cudaGetSymbolAddress((void**)&xh, g_xh);   cudaGetSymbolAddress((void**)&xl, g_xl);
    cudaGetSymbolAddress((void**)&Ch, g_Ch);   cudaGetSymbolAddress((void**)&Cl, g_Cl);
    cudaGetSymbolAddress((void**)&Ph, g_Ph);   cudaGetSymbolAddress((void**)&Pl, g_Pl);
    cudaGetSymbolAddress((void**)&Qh, g_Qh);   cudaGetSymbolAddress((void**)&Ql, g_Ql);
    cudaGetSymbolAddress((void**)&Rh, g_Rh);   cudaGetSymbolAddress((void**)&Rl, g_Rl);
    cudaGetSymbolAddress((void**)&Wph, g_Wph); cudaGetSymbolAddress((void**)&Wpl, g_Wpl);
    cudaGetSymbolAddress((void**)&Wgh, g_Wgh); cudaGetSymbolAddress((void**)&Wgl, g_Wgl);
    cudaGetSymbolAddress((void**)&Wth, g_Wth); cudaGetSymbolAddress((void**)&Wtl, g_Wtl);

    cudaFuncSetAttribute(gemm_bf16x3, cudaFuncAttributeMaxDynamicSharedMemorySize, GEMM_SMEM);
    cudaFuncSetAttribute(syrk_bf16x3, cudaFuncAttributeMaxDynamicSharedMemorySize, GEMM_SMEM);

    const float scale = 1.0f / 32.0f;  // 1/sqrt(1024)

    // conversions
    const int nx = BATCH * NSEQ * FDIM;
    conv_x_kernel<<<nx / 8 / 256, 256>>>((const float4*)x, (__nv_bfloat162*)xh, (__nv_bfloat162*)xl);
    conv_pair_kernel<<<(LDIM * FDIM) / 256, 256>>>(Wp, Wph, Wpl, LDIM * FDIM);
    conv_pair_kernel<<<(ODIM * FDIM) / 256, 256>>>(Wg, Wgh, Wgl, ODIM * FDIM);
    conv_T_kernel<<<dim3(FDIM / 32, LDIM / 32), dim3(32, 8)>>>(Wt, Wth, Wtl, LDIM, FDIM);

    const long long sX = (long long)NSEQ * FDIM;
    const long long sC = (long long)FDIM * FDIM;
    const long long sP = (long long)LDIM * FDIM;
    const long long sQ = (long long)ODIM * LDIM;
    const long long sR = (long long)ODIM * FDIM;

    // 1) C = x^T x, upper-triangle blocks (36 of 64), then mirror
    syrk_bf16x3<<<dim3(36, 1, BATCH), 256, GEMM_SMEM>>>(xh, xl, Ch, Cl);
    mirror_kernel<<<dim3(528, BATCH), dim3(32, 8)>>>(Ch, Cl);

    // 2) P[l,f2] = scale * sum_f1 Wphi[l,f1]*C[f2,f1]   M=256,N=1024,K=1024
    gemm_bf16x3<<<dim3(8, 2, BATCH), 256, GEMM_SMEM>>>(
        Wph, Wpl, Ch, Cl, nullptr, Ph, Pl, FDIM, FDIM, 0, sC, sP, scale, 1);

    // 3) QT[o,l] = sum_f Wg[o,f]*P[l,f]                 M=1024,N=256,K=1024
    gemm_bf16x3<<<dim3(2, 8, BATCH), 256, GEMM_SMEM>>>(
        Wgh, Wgl, Ph, Pl, nullptr, Qh, Ql, LDIM, FDIM, 0, sP, sQ, 1.0f, 1);

    // 4) RT[o,f] = sum_l QT[o,l]*WthetaT[f,l]           M=1024,N=1024,K=256
    gemm_bf16x3<<<dim3(8, 8, BATCH), 256, GEMM_SMEM>>>(
        Qh, Ql, Wth, Wtl, nullptr, Rh, Rl, FDIM, LDIM, sQ, 0, sR, 1.0f, 1);

    // 5) out[s,o] = sum_f x[s,f]*RT[o,f]                M=4096,N=1024,K=1024
    gemm_bf16x3<<<dim3(8, 32, BATCH), 256, GEMM_SMEM>>>(
        xh, xl, Rh, Rl, out, nullptr, nullptr, ODIM, FDIM, sX, sR, sX, 1.0f, 0);
}

// round 5
// speedup vs baseline: 3.9768x; 1.0201x over previous
#include <cuda_runtime.h>
#include <cuda_bf16.h>
#include <math.h>
#include <stdint.h>

// ---------------- problem constants ----------------
#define BATCH 8
#define NSEQ  4096
#define FDIM  1024
#define LDIM  256
#define ODIM  1024

// ---------------- scratch (device globals) ----------------
__device__ __nv_bfloat16 g_xh [BATCH * NSEQ * FDIM];
__device__ __nv_bfloat16 g_xl [BATCH * NSEQ * FDIM];
__device__ __nv_bfloat16 g_Ch [BATCH * FDIM * FDIM];
__device__ __nv_bfloat16 g_Cl [BATCH * FDIM * FDIM];
__device__ __nv_bfloat16 g_Ph [BATCH * LDIM * FDIM];
__device__ __nv_bfloat16 g_Pl [BATCH * LDIM * FDIM];
__device__ __nv_bfloat16 g_Qh [BATCH * ODIM * LDIM];
__device__ __nv_bfloat16 g_Ql [BATCH * ODIM * LDIM];
__device__ __nv_bfloat16 g_Rh [BATCH * ODIM * FDIM];
__device__ __nv_bfloat16 g_Rl [BATCH * ODIM * FDIM];
__device__ __nv_bfloat16 g_Wph[LDIM * FDIM];
__device__ __nv_bfloat16 g_Wpl[LDIM * FDIM];
__device__ __nv_bfloat16 g_Wgh[ODIM * FDIM];
__device__ __nv_bfloat16 g_Wgl[ODIM * FDIM];
__device__ __nv_bfloat16 g_Wth[FDIM * LDIM];
__device__ __nv_bfloat16 g_Wtl[FDIM * LDIM];

// ---------------- PTX helpers ----------------
__device__ __forceinline__ uint32_t smem_u32(const void* p) {
    uint32_t a;
    asm("{ .reg .u64 t; cvta.to.shared.u64 t, %1; cvt.u32.u64 %0, t; }" : "=r"(a) : "l"(p));
    return a;
}
__device__ __forceinline__ void cp16(uint32_t dst, const void* src) {
    asm volatile("cp.async.cg.shared.global [%0], [%1], 16;\n" :: "r"(dst), "l"(src));
}
#define CP_COMMIT()  asm volatile("cp.async.commit_group;\n" ::: "memory")
#define CP_WAIT0()   asm volatile("cp.async.wait_group 0;\n" ::: "memory")
#define CP_WAIT1()   asm volatile("cp.async.wait_group 1;\n" ::: "memory")
#define CP_WAIT2()   asm volatile("cp.async.wait_group 2;\n" ::: "memory")

__device__ __forceinline__ void ldsm4(uint32_t* r, uint32_t addr) {
    asm volatile("ldmatrix.sync.aligned.m8n8.x4.shared.b16 {%0,%1,%2,%3}, [%4];"
        : "=r"(r[0]), "=r"(r[1]), "=r"(r[2]), "=r"(r[3]) : "r"(addr));
}
__device__ __forceinline__ void ldsm4t(uint32_t* r, uint32_t addr) {
    asm volatile("ldmatrix.sync.aligned.m8n8.x4.trans.shared.b16 {%0,%1,%2,%3}, [%4];"
        : "=r"(r[0]), "=r"(r[1]), "=r"(r[2]), "=r"(r[3]) : "r"(addr));
}
__device__ __forceinline__ void mma16816(float* d, const uint32_t* a, const uint32_t* b) {
    asm volatile(
        "mma.sync.aligned.m16n8k16.row.col.f32.bf16.bf16.f32 "
        "{%0,%1,%2,%3}, {%4,%5,%6,%7}, {%8,%9}, {%0,%1,%2,%3};"
        : "+f"(d[0]), "+f"(d[1]), "+f"(d[2]), "+f"(d[3])
        : "r"(a[0]), "r"(a[1]), "r"(a[2]), "r"(a[3]), "r"(b[0]), "r"(b[1]));
}
__device__ __forceinline__ uint32_t sw128(uint32_t off) {
    return off ^ ((off >> 3) & 0x70);
}
__device__ __forceinline__ void split_bf16(float v, __nv_bfloat16& h, __nv_bfloat16& l) {
    h = __float2bfloat16(v);
    l = __float2bfloat16(v - __bfloat162float(h));
}

// smem: 3 stages x 64KB. Stage: Ah | Al | Bh | Bl (16KB each)
#define STAGE_BYTES 65536
#define OFF_AH 0
#define OFF_AL 16384
#define OFF_BH 32768
#define OFF_BL 49152
#define GEMM_SMEM (3 * STAGE_BYTES)

// ============================================================================
// Generic HMMA GEMM: D[m,n] = alpha * sum_k A[m,k]*B[n,k]  (bf16x3, batched)
// K-major operands. mode 0: fp32 out; mode 1: bf16 hi/lo out.
// Pipelined: 3-stage cp.async + register double-buffered fragments.
// ============================================================================
__global__ void __launch_bounds__(256, 1)
gemm_bf16x3(const __nv_bfloat16* __restrict__ Ah, const __nv_bfloat16* __restrict__ Al,
            const __nv_bfloat16* __restrict__ Bh, const __nv_bfloat16* __restrict__ Bl,
            float* __restrict__ Df, __nv_bfloat16* __restrict__ Dh, __nv_bfloat16* __restrict__ Dl,
            int N, int K,
            long long sA, long long sB, long long sD,
            float alpha, int mode)
{
    extern __shared__ char smem[];
    const int b = blockIdx.z;
    Ah += (long long)b * sA;  Al += (long long)b * sA;
    Bh += (long long)b * sB;  Bl += (long long)b * sB;

    const int m0 = blockIdx.y * 128;
    const int n0 = blockIdx.x * 128;
    const int tid = (int)threadIdx.x;
    const int wid = tid >> 5;
    const int lid = tid & 31;
    const int wm = (wid >> 2) * 64;
    const int wn = (wid & 3) * 32;

    const uint32_t sb = smem_u32(smem);
    const int nch = K >> 6;

    auto load_chunk = [&](int kc, int stage) {
        const long long kofs = (long long)kc * 64;
        const uint32_t sbase = sb + stage * STAGE_BYTES;
#pragma unroll
        for (int j = 0; j < 4; j++) {
            int idx = j * 256 + tid;
            int r   = idx >> 3;
            int cb  = (idx & 7) << 4;
            uint32_t sw = sw128((uint32_t)(r * 128 + cb));
            long long ea = (long long)(m0 + r) * K + kofs + (cb >> 1);
            long long eb = (long long)(n0 + r) * K + kofs + (cb >> 1);
            cp16(sbase + OFF_AH + sw, Ah + ea);
            cp16(sbase + OFF_AL + sw, Al + ea);
            cp16(sbase + OFF_BH + sw, Bh + eb);
            cp16(sbase + OFF_BL + sw, Bl + eb);
        }
        CP_COMMIT();
    };

    float acc[4][4][4];
#pragma unroll
    for (int i = 0; i < 4; i++)
#pragma unroll
        for (int j = 0; j < 4; j++)
#pragma unroll
            for (int c = 0; c < 4; c++) acc[i][j][c] = 0.0f;

    const int a_row = wm + (lid & 15);
    const int a_cb  = (lid >> 4) * 16;
    const int b_row = wn + (lid & 7) + ((lid >> 4) & 1) * 8;
    const int b_cb  = ((lid >> 3) & 1) * 16;

    uint32_t ahf[2][4][4], alf[2][4][4], bhf[2][2][4], blf[2][2][4];

    auto ldfrags = [&](int k16, int buf, uint32_t sbase) {
        const int kb = k16 * 32;
#pragma unroll
        for (int mt = 0; mt < 4; mt++) {
            uint32_t sw = sw128((uint32_t)((a_row + mt * 16) * 128 + kb + a_cb));
            ldsm4(ahf[buf][mt], sbase + OFF_AH + sw);
            ldsm4(alf[buf][mt], sbase + OFF_AL + sw);
        }
#pragma unroll
        for (int np = 0; np < 2; np++) {
            uint32_t sw = sw128((uint32_t)((b_row + np * 16) * 128 + kb + b_cb));
            ldsm4(bhf[buf][np], sbase + OFF_BH + sw);
            ldsm4(blf[buf][np], sbase + OFF_BL + sw);
        }
    };

    load_chunk(0, 0);
    if (nch > 1) load_chunk(1, 1);
    if (nch > 2) load_chunk(2, 2);

    for (int i = 0; i < nch; i++) {
        const int s = i % 3;
        const int rem = nch - 1 - i;
        if (rem >= 2)      { CP_WAIT2(); }
        else if (rem == 1) { CP_WAIT1(); }
        else               { CP_WAIT0(); }
        __syncthreads();

        const uint32_t sbase = sb + s * STAGE_BYTES;
        ldfrags(0, 0, sbase);
        int cur = 0;
#pragma unroll
        for (int k16 = 0; k16 < 4; k16++) {
            if (k16 < 3) ldfrags(k16 + 1, cur ^ 1, sbase);
            if (k16 == 3) {
                __syncthreads();               // all smem reads for this chunk done
                if (i + 3 < nch) load_chunk(i + 3, s);
            }
#pragma unroll
            for (int p = 0; p < 3; p++) {
#pragma unroll
                for (int mt = 0; mt < 4; mt++) {
                    const uint32_t* af = (p == 2) ? alf[cur][mt] : ahf[cur][mt];
#pragma unroll
                    for (int nt = 0; nt < 4; nt++) {
                        const uint32_t* bf = (p == 1) ? &blf[cur][nt >> 1][(nt & 1) * 2]
                                                      : &bhf[cur][nt >> 1][(nt & 1) * 2];
                        mma16816(acc[mt][nt], af, bf);
                    }
                }
            }
            cur ^= 1;
        }
    }

    const int er = lid >> 2;
    const int ec = (lid & 3) * 2;
#pragma unroll
    for (int mt = 0; mt < 4; mt++) {
#pragma unroll
        for (int nt = 0; nt < 4; nt++) {
            const long long row0 = m0 + wm + mt * 16 + er;
            const long long col  = n0 + wn + nt * 8 + ec;
            if (mode == 0) {
                float2 v0, v1;
                v0.x = acc[mt][nt][0] * alpha; v0.y = acc[mt][nt][1] * alpha;
                v1.x = acc[mt][nt][2] * alpha; v1.y = acc[mt][nt][3] * alpha;
                *(float2*)(Df + (long long)b * sD + row0 * N + col)       = v0;
                *(float2*)(Df + (long long)b * sD + (row0 + 8) * N + col) = v1;
            } else {
                float p0 = acc[mt][nt][0] * alpha, p1 = acc[mt][nt][1] * alpha;
                float p2 = acc[mt][nt][2] * alpha, p3 = acc[mt][nt][3] * alpha;
                __nv_bfloat16 h0, h1, h2, h3, l0, l1, l2, l3;
                split_bf16(p0, h0, l0); split_bf16(p1, h1, l1);
                split_bf16(p2, h2, l2); split_bf16(p3, h3, l3);
                long long base = (long long)b * sD;
                *(__nv_bfloat162*)(Dh + base + row0 * N + col)       = __nv_bfloat162(h0, h1);
                *(__nv_bfloat162*)(Dh + base + (row0 + 8) * N + col) = __nv_bfloat162(h2, h3);
                *(__nv_bfloat162*)(Dl + base + row0 * N + col)       = __nv_bfloat162(l0, l1);
                *(__nv_bfloat162*)(Dl + base + (row0 + 8) * N + col) = __nv_bfloat162(l2, l3);
            }
        }
    }
}

// ============================================================================
// SYRK: C = x^T x, upper-triangle blocks only. x [S,F]; trans-ldmatrix frags.
// Same pipelining as gemm_bf16x3.
// ============================================================================
__global__ void __launch_bounds__(256, 1)
syrk_bf16x3(const __nv_bfloat16* __restrict__ xh, const __nv_bfloat16* __restrict__ xl,
            __nv_bfloat16* __restrict__ Ch, __nv_bfloat16* __restrict__ Cl)
{
    extern __shared__ char smem[];
    int t = blockIdx.x, by = 0;
    while (t >= 8 - by) { t -= 8 - by; by++; }
    const int bx = by + t;
    const bool diag = (bx == by);

    const int b = blockIdx.z;
    const long long xoff = (long long)b * NSEQ * FDIM;
    const int m0 = by * 128, n0 = bx * 128;
    const int tid = (int)threadIdx.x;
    const int wid = tid >> 5;
    const int lid = tid & 31;
    const int wm = (wid >> 2) * 64;
    const int wn = (wid & 3) * 32;

    const uint32_t sb = smem_u32(smem);
    const uint32_t offBH = diag ? OFF_AH : OFF_BH;
    const uint32_t offBL = offBH + 16384;

    auto load_chunk = [&](int kc, int stage) {
        const uint32_t sbase = sb + stage * STAGE_BYTES;
        const long long s0 = (long long)kc * 64;
#pragma unroll
        for (int j = 0; j < 4; j++) {
            int idx = j * 256 + tid;
            int r   = idx >> 4;
            int cb  = (idx & 15) << 4;
            uint32_t sw = (uint32_t)(r * 256 + cb) ^ (uint32_t)((r & 7) << 4);
            long long g = xoff + (s0 + r) * FDIM;
            cp16(sbase + OFF_AH + sw, xh + g + m0 + (cb >> 1));
            cp16(sbase + OFF_AL + sw, xl + g + m0 + (cb >> 1));
            if (!diag) {
                cp16(sbase + OFF_BH + sw, xh + g + n0 + (cb >> 1));
                cp16(sbase + OFF_BL + sw, xl + g + n0 + (cb >> 1));
            }
        }
        CP_COMMIT();
    };

    float acc[4][4][4];
#pragma unroll
    for (int i = 0; i < 4; i++)
#pragma unroll
        for (int j = 0; j < 4; j++)
#pragma unroll
            for (int c = 0; c < 4; c++) acc[i][j][c] = 0.0f;

    const int a_krow  = ((lid >> 4) & 1) * 8 + (lid & 7);
    const int a_mbyte = ((lid >> 3) & 1) * 16;
    const int b_krow  = ((lid >> 3) & 1) * 8 + (lid & 7);
    const int b_nbyte = ((lid >> 4) & 1) * 16;

    uint32_t ahf[2][4][4], alf[2][4][4], bhf[2][2][4], blf[2][2][4];

    auto ldfrags = [&](int k16, int buf, uint32_t sbase) {
#pragma unroll
        for (int mt = 0; mt < 4; mt++) {
            uint32_t off = (uint32_t)((k16 * 16 + a_krow) * 256 + (wm + mt * 16) * 2 + a_mbyte);
            off ^= (uint32_t)((a_krow & 7) << 4);
            ldsm4t(ahf[buf][mt], sbase + OFF_AH + off);
            ldsm4t(alf[buf][mt], sbase + OFF_AL + off);
        }
#pragma unroll
        for (int np = 0; np < 2; np++) {
            uint32_t off = (uint32_t)((k16 * 16 + b_krow) * 256 + (wn + np * 16) * 2 + b_nbyte);
            off ^= (uint32_t)((b_krow & 7) << 4);
            ldsm4t(bhf[buf][np], sbase + offBH + off);
            ldsm4t(blf[buf][np], sbase + offBL + off);
        }
    };

    const int nch = NSEQ >> 6;   // 64
    load_chunk(0, 0);
    load_chunk(1, 1);
    load_chunk(2, 2);

    for (int i = 0; i < nch; i++) {
        const int s = i % 3;
        const int rem = nch - 1 - i;
        if (rem >= 2)      { CP_WAIT2(); }
        else if (rem == 1) { CP_WAIT1(); }
        else               { CP_WAIT0(); }
        __syncthreads();

        const uint32_t sbase = sb + s * STAGE_BYTES;
        ldfrags(0, 0, sbase);
        int cur = 0;
#pragma unroll
        for (int k16 = 0; k16 < 4; k16++) {
            if (k16 < 3) ldfrags(k16 + 1, cur ^ 1, sbase);
            if (k16 == 3) {
                __syncthreads();
                if (i + 3 < nch) load_chunk(i + 3, s);
            }
#pragma unroll
            for (int p = 0; p < 3; p++) {
#pragma unroll
                for (int mt = 0; mt < 4; mt++) {
                    const uint32_t* af = (p == 2) ? alf[cur][mt] : ahf[cur][mt];
#pragma unroll
                    for (int nt = 0; nt < 4; nt++) {
                        const uint32_t* bf = (p == 1) ? &blf[cur][nt >> 1][(nt & 1) * 2]
                                                      : &bhf[cur][nt >> 1][(nt & 1) * 2];
                        mma16816(acc[mt][nt], af, bf);
                    }
                }
            }
            cur ^= 1;
        }
    }

    const int er = lid >> 2;
    const int ec = (lid & 3) * 2;
    const long long base = (long long)b * FDIM * FDIM;
#pragma unroll
    for (int mt = 0; mt < 4; mt++) {
#pragma unroll
        for (int nt = 0; nt < 4; nt++) {
            const long long row0 = m0 + wm + mt * 16 + er;
            const long long col  = n0 + wn + nt * 8 + ec;
            float p0 = acc[mt][nt][0], p1 = acc[mt][nt][1];
            float p2 = acc[mt][nt][2], p3 = acc[mt][nt][3];
            __nv_bfloat16 h0, h1, h2, h3, l0, l1, l2, l3;
            split_bf16(p0, h0, l0); split_bf16(p1, h1, l1);
            split_bf16(p2, h2, l2); split_bf16(p3, h3, l3);
            *(__nv_bfloat162*)(Ch + base + row0 * FDIM + col)       = __nv_bfloat162(h0, h1);
            *(__nv_bfloat162*)(Ch + base + (row0 + 8) * FDIM + col) = __nv_bfloat162(h2, h3);
            *(__nv_bfloat162*)(Cl + base + row0 * FDIM + col)       = __nv_bfloat162(l0, l1);
            *(__nv_bfloat162*)(Cl + base + (row0 + 8) * FDIM + col) = __nv_bfloat162(l2, l3);
        }
    }
}

// ============================================================================
// Mirror upper triangle of C into lower triangle (hi and lo).
// ============================================================================
__global__ void mirror_kernel(__nv_bfloat16* __restrict__ Ch, __nv_bfloat16* __restrict__ Cl)
{
    int t = blockIdx.x, ty = 0;
    while (t >= 32 - ty) { t -= 32 - ty; ty++; }
    const int tx = ty + t;
    const int b = blockIdx.y;
    const long long base = (long long)b * FDIM * FDIM;
    __shared__ __nv_bfloat16 sh[32][33];
    __shared__ __nv_bfloat16 sl[32][33];
    const int x_ = threadIdx.x, y = threadIdx.y;
    const int r0 = ty * 32, c0 = tx * 32;
#pragma unroll
    for (int r = 0; r < 4; r++) {
        int i = r0 + y + r * 8;
        sh[y + r * 8][x_] = Ch[base + (long long)i * FDIM + c0 + x_];
        sl[y + r * 8][x_] = Cl[base + (long long)i * FDIM + c0 + x_];
    }
    __syncthreads();
#pragma unroll
    for (int r = 0; r < 4; r++) {
        int j = c0 + y + r * 8;
        int i = r0 + x_;
        if (j > i) {
            Ch[base + (long long)j * FDIM + i] = sh[x_][y + r * 8];
            Cl[base + (long long)j * FDIM + i] = sl[x_][y + r * 8];
        }
    }
}

// ---------------- conversion kernels ----------------
__global__ void conv_x_kernel(const float4* __restrict__ x,
                              __nv_bfloat162* __restrict__ xh2, __nv_bfloat162* __restrict__ xl2)
{
    const int i = blockIdx.x * blockDim.x + threadIdx.x;
#pragma unroll
    for (int p = 0; p < 2; p++) {
        float4 v = x[i * 2 + p];
        __nv_bfloat16 h0, h1, h2, h3, l0, l1, l2, l3;
        split_bf16(v.x, h0, l0); split_bf16(v.y, h1, l1);
        split_bf16(v.z, h2, l2); split_bf16(v.w, h3, l3);
        xh2[i * 4 + p * 2 + 0] = __nv_bfloat162(h0, h1);
        xh2[i * 4 + p * 2 + 1] = __nv_bfloat162(h2, h3);
        xl2[i * 4 + p * 2 + 0] = __nv_bfloat162(l0, l1);
        xl2[i * 4 + p * 2 + 1] = __nv_bfloat162(l2, l3);
    }
}

__global__ void conv_pair_kernel(const float* __restrict__ in,
                                 __nv_bfloat16* __restrict__ oh, __nv_bfloat16* __restrict__ ol, int n)
{
    int i = blockIdx.x * blockDim.x + threadIdx.x;
    if (i < n) {
        __nv_bfloat16 h, l; split_bf16(in[i], h, l);
        oh[i] = h; ol[i] = l;
    }
}

__global__ void conv_T_kernel(const float* __restrict__ in,
                              __nv_bfloat16* __restrict__ oh, __nv_bfloat16* __restrict__ ol,
                              int R, int C)
{
    __shared__ float t[32][33];
    const int r0 = blockIdx.y * 32;
    const int c0 = blockIdx.x * 32;
    const int tx = threadIdx.x, ty = threadIdx.y;
#pragma unroll
    for (int r = 0; r < 4; r++)
        t[ty + r * 8][tx] = in[(long long)(r0 + ty + r * 8) * C + c0 + tx];
    __syncthreads();
#pragma unroll
    for (int r = 0; r < 4; r++) {
        float v = t[tx][ty + r * 8];
        __nv_bfloat16 h, l; split_bf16(v, h, l);
        oh[(long long)(c0 + ty + r * 8) * R + r0 + tx] = h;
        ol[(long long)(c0 + ty + r * 8) * R + r0 + tx] = l;
    }
}

// ---------------- launcher ----------------
extern "C" void kernel_launch(void* const* d_in, const int* in_sizes, int n_in,
                              void* d_out, int out_size)
{
    const float* x  = (const float*)d_in[0];
    const float* Wt = (const float*)d_in[1];
    const float* Wp = (const float*)d_in[2];
    const float* Wg = (const float*)d_in[3];
    float* out = (float*)d_out;

    __nv_bfloat16 *xh, *xl, *Ch, *Cl, *Ph, *Pl, *Qh, *Ql, *Rh, *Rl;
    __nv_bfloat16 *Wph, *Wpl, *Wgh, *Wgl, *Wth, *Wtl;
    cudaGetSymbolAddress((void**)&xh, g_xh);   cudaGetSymbolAddress((void**)&xl, g_xl);
    cudaGetSymbolAddress((void**)&Ch, g_Ch);   cudaGetSymbolAddress((void**)&Cl, g_Cl);
    cudaGetSymbolAddress((void**)&Ph, g_Ph);   cudaGetSymbolAddress((void**)&Pl, g_Pl);
    cudaGetSymbolAddress((void**)&Qh, g_Qh);   cudaGetSymbolAddress((void**)&Ql, g_Ql);
    cudaGetSymbolAddress((void**)&Rh, g_Rh);   cudaGetSymbolAddress((void**)&Rl, g_Rl);
    cudaGetSymbolAddress((void**)&Wph, g_Wph); cudaGetSymbolAddress((void**)&Wpl, g_Wpl);
    cudaGetSymbolAddress((void**)&Wgh, g_Wgh); cudaGetSymbolAddress((void**)&Wgl, g_Wgl);
    cudaGetSymbolAddress((void**)&Wth, g_Wth); cudaGetSymbolAddress((void**)&Wtl, g_Wtl);

    cudaFuncSetAttribute(gemm_bf16x3, cudaFuncAttributeMaxDynamicSharedMemorySize, GEMM_SMEM);
    cudaFuncSetAttribute(syrk_bf16x3, cudaFuncAttributeMaxDynamicSharedMemorySize, GEMM_SMEM);

    const float scale = 1.0f / 32.0f;  // 1/sqrt(1024)

    // conversions — 5 launches so SYRK is launch #6 (ncu -s 5 -c 1 captures it)
    const int nx = BATCH * NSEQ * FDIM;
    conv_x_kernel<<<nx / 8 / 256, 256>>>((const float4*)x, (__nv_bfloat162*)xh, (__nv_bfloat162*)xl);
    conv_pair_kernel<<<(LDIM * FDIM) / 256, 256>>>(Wp, Wph, Wpl, LDIM * FDIM);
    const int half = (ODIM * FDIM) / 2;
    conv_pair_kernel<<<half / 256, 256>>>(Wg, Wgh, Wgl, half);
    conv_pair_kernel<<<half / 256, 256>>>(Wg + half, Wgh + half, Wgl + half, half);
    conv_T_kernel<<<dim3(FDIM / 32, LDIM / 32), dim3(32, 8)>>>(Wt, Wth, Wtl, LDIM, FDIM);

    const long long sX = (long long)NSEQ * FDIM;
    const long long sC = (long long)FDIM * FDIM;
    const long long sP = (long long)LDIM * FDIM;
    const long long sQ = (long long)ODIM * LDIM;
    const long long sR = (long long)ODIM * FDIM;

    // 1) C = x^T x, upper-triangle blocks, then mirror
    syrk_bf16x3<<<dim3(36, 1, BATCH), 256, GEMM_SMEM>>>(xh, xl, Ch, Cl);
    mirror_kernel<<<dim3(528, BATCH), dim3(32, 8)>>>(Ch, Cl);

    // 2) P = scale * Wphi @ C
    gemm_bf16x3<<<dim3(8, 2, BATCH), 256, GEMM_SMEM>>>(
        Wph, Wpl, Ch, Cl, nullptr, Ph, Pl, FDIM, FDIM, 0, sC, sP, scale, 1);

    // 3) QT = Wg @ P^T-form
    gemm_bf16x3<<<dim3(2, 8, BATCH), 256, GEMM_SMEM>>>(
        Wgh, Wgl, Ph, Pl, nullptr, Qh, Ql, LDIM, FDIM, 0, sP, sQ, 1.0f, 1);

    // 4) RT = QT @ WthetaT
    gemm_bf16x3<<<dim3(8, 8, BATCH), 256, GEMM_SMEM>>>(
        Qh, Ql, Wth, Wtl, nullptr, Rh, Rl, FDIM, LDIM, sQ, 0, sR, 1.0f, 1);

    // 5) out = x @ RT
    gemm_bf16x3<<<dim3(8, 32, BATCH), 256, GEMM_SMEM>>>(
        xh, xl, Rh, Rl, out, nullptr, nullptr, ODIM, FDIM, sX, sR, sX, 1.0f, 0);
}

// round 6
// speedup vs baseline: 5.3546x; 1.3464x over previous
#include <cuda_runtime.h>
#include <cuda_bf16.h>
#include <math.h>
#include <stdint.h>

// ---------------- problem constants ----------------
#define BATCH 8
#define NSEQ  4096
#define FDIM  1024
#define LDIM  256
#define ODIM  1024

// ---------------- scratch (device globals) ----------------
__device__ __nv_bfloat16 g_xh [BATCH * NSEQ * FDIM];   // x hi [B,S,F]
__device__ __nv_bfloat16 g_xl [BATCH * NSEQ * FDIM];
__device__ __nv_bfloat16 g_Th [BATCH * NSEQ * LDIM];   // theta = x Wth^T [B,S,L]
__device__ __nv_bfloat16 g_Tl [BATCH * NSEQ * LDIM];
__device__ __nv_bfloat16 g_Ch [BATCH * FDIM * FDIM];   // C = x^T x (symmetric)
__device__ __nv_bfloat16 g_Cl [BATCH * FDIM * FDIM];
__device__ __nv_bfloat16 g_Ph [BATCH * LDIM * FDIM];   // P = scale*Wphi*C [B,L,F]
__device__ __nv_bfloat16 g_Pl [BATCH * LDIM * FDIM];
__device__ __nv_bfloat16 g_Qh [BATCH * ODIM * LDIM];   // QT [B,O,L]
__device__ __nv_bfloat16 g_Ql [BATCH * ODIM * LDIM];
__device__ __nv_bfloat16 g_Wth[LDIM * FDIM];           // Wtheta [L,F] K-major
__device__ __nv_bfloat16 g_Wtl[LDIM * FDIM];
__device__ __nv_bfloat16 g_Wph[LDIM * FDIM];
__device__ __nv_bfloat16 g_Wpl[LDIM * FDIM];
__device__ __nv_bfloat16 g_Wgh[ODIM * FDIM];
__device__ __nv_bfloat16 g_Wgl[ODIM * FDIM];

// ---------------- PTX helpers ----------------
__device__ __forceinline__ uint32_t smem_u32(const void* p) {
    uint32_t a;
    asm("{ .reg .u64 t; cvta.to.shared.u64 t, %1; cvt.u32.u64 %0, t; }" : "=r"(a) : "l"(p));
    return a;
}
__device__ __forceinline__ void cp16(uint32_t dst, const void* src) {
    asm volatile("cp.async.cg.shared.global [%0], [%1], 16;\n" :: "r"(dst), "l"(src));
}
#define CP_COMMIT()  asm volatile("cp.async.commit_group;\n" ::: "memory")
#define CP_WAIT0()   asm volatile("cp.async.wait_group 0;\n" ::: "memory")
#define CP_WAIT1()   asm volatile("cp.async.wait_group 1;\n" ::: "memory")
#define CP_WAIT2()   asm volatile("cp.async.wait_group 2;\n" ::: "memory")

__device__ __forceinline__ void ldsm4(uint32_t* r, uint32_t addr) {
    asm volatile("ldmatrix.sync.aligned.m8n8.x4.shared.b16 {%0,%1,%2,%3}, [%4];"
        : "=r"(r[0]), "=r"(r[1]), "=r"(r[2]), "=r"(r[3]) : "r"(addr));
}
__device__ __forceinline__ void ldsm4t(uint32_t* r, uint32_t addr) {
    asm volatile("ldmatrix.sync.aligned.m8n8.x4.trans.shared.b16 {%0,%1,%2,%3}, [%4];"
        : "=r"(r[0]), "=r"(r[1]), "=r"(r[2]), "=r"(r[3]) : "r"(addr));
}
__device__ __forceinline__ void mma16816(float* d, const uint32_t* a, const uint32_t* b) {
    asm volatile(
        "mma.sync.aligned.m16n8k16.row.col.f32.bf16.bf16.f32 "
        "{%0,%1,%2,%3}, {%4,%5,%6,%7}, {%8,%9}, {%0,%1,%2,%3};"
        : "+f"(d[0]), "+f"(d[1]), "+f"(d[2]), "+f"(d[3])
        : "r"(a[0]), "r"(a[1]), "r"(a[2]), "r"(a[3]), "r"(b[0]), "r"(b[1]));
}
__device__ __forceinline__ uint32_t sw128(uint32_t off) {
    return off ^ ((off >> 3) & 0x70);
}
__device__ __forceinline__ void split_bf16(float v, __nv_bfloat16& h, __nv_bfloat16& l) {
    h = __float2bfloat16(v);
    l = __float2bfloat16(v - __bfloat162float(h));
}

// smem: 3 stages x 64KB. Stage: Ah | Al | Bh | Bl (16KB each)
#define STAGE_BYTES 65536
#define OFF_AH 0
#define OFF_AL 16384
#define OFF_BH 32768
#define OFF_BL 49152
#define GEMM_SMEM (3 * STAGE_BYTES)

// ============================================================================
// Generic HMMA GEMM: D[m,n] = alpha * sum_k A[m,k]*B[n,k]  (bf16x3, batched)
// K-major operands. mode 0: fp32 out; mode 1: bf16 hi/lo out.
// 3-stage cp.async + register double-buffered fragments.
// ============================================================================
__global__ void __launch_bounds__(256, 1)
gemm_bf16x3(const __nv_bfloat16* __restrict__ Ah, const __nv_bfloat16* __restrict__ Al,
            const __nv_bfloat16* __restrict__ Bh, const __nv_bfloat16* __restrict__ Bl,
            float* __restrict__ Df, __nv_bfloat16* __restrict__ Dh, __nv_bfloat16* __restrict__ Dl,
            int N, int K,
            long long sA, long long sB, long long sD,
            float alpha, int mode)
{
    extern __shared__ char smem[];
    const int b = blockIdx.z;
    Ah += (long long)b * sA;  Al += (long long)b * sA;
    Bh += (long long)b * sB;  Bl += (long long)b * sB;

    const int m0 = blockIdx.y * 128;
    const int n0 = blockIdx.x * 128;
    const int tid = (int)threadIdx.x;
    const int wid = tid >> 5;
    const int lid = tid & 31;
    const int wm = (wid >> 2) * 64;
    const int wn = (wid & 3) * 32;

    const uint32_t sb = smem_u32(smem);
    const int nch = K >> 6;

    auto load_chunk = [&](int kc, int stage) {
        const long long kofs = (long long)kc * 64;
        const uint32_t sbase = sb + stage * STAGE_BYTES;
#pragma unroll
        for (int j = 0; j < 4; j++) {
            int idx = j * 256 + tid;
            int r   = idx >> 3;
            int cb  = (idx & 7) << 4;
            uint32_t sw = sw128((uint32_t)(r * 128 + cb));
            long long ea = (long long)(m0 + r) * K + kofs + (cb >> 1);
            long long eb = (long long)(n0 + r) * K + kofs + (cb >> 1);
            cp16(sbase + OFF_AH + sw, Ah + ea);
            cp16(sbase + OFF_AL + sw, Al + ea);
            cp16(sbase + OFF_BH + sw, Bh + eb);
            cp16(sbase + OFF_BL + sw, Bl + eb);
        }
        CP_COMMIT();
    };

    float acc[4][4][4];
#pragma unroll
    for (int i = 0; i < 4; i++)
#pragma unroll
        for (int j = 0; j < 4; j++)
#pragma unroll
            for (int c = 0; c < 4; c++) acc[i][j][c] = 0.0f;

    const int a_row = wm + (lid & 15);
    const int a_cb  = (lid >> 4) * 16;
    const int b_row = wn + (lid & 7) + ((lid >> 4) & 1) * 8;
    const int b_cb  = ((lid >> 3) & 1) * 16;

    uint32_t ahf[2][4][4], alf[2][4][4], bhf[2][2][4], blf[2][2][4];

    auto ldfrags = [&](int k16, int buf, uint32_t sbase) {
        const int kb = k16 * 32;
#pragma unroll
        for (int mt = 0; mt < 4; mt++) {
            uint32_t sw = sw128((uint32_t)((a_row + mt * 16) * 128 + kb + a_cb));
            ldsm4(ahf[buf][mt], sbase + OFF_AH + sw);
            ldsm4(alf[buf][mt], sbase + OFF_AL + sw);
        }
#pragma unroll
        for (int np = 0; np < 2; np++) {
            uint32_t sw = sw128((uint32_t)((b_row + np * 16) * 128 + kb + b_cb));
            ldsm4(bhf[buf][np], sbase + OFF_BH + sw);
            ldsm4(blf[buf][np], sbase + OFF_BL + sw);
        }
    };

    load_chunk(0, 0);
    if (nch > 1) load_chunk(1, 1);
    if (nch > 2) load_chunk(2, 2);

    for (int i = 0; i < nch; i++) {
        const int s = i % 3;
        const int rem = nch - 1 - i;
        if (rem >= 2)      { CP_WAIT2(); }
        else if (rem == 1) { CP_WAIT1(); }
        else               { CP_WAIT0(); }
        __syncthreads();

        const uint32_t sbase = sb + s * STAGE_BYTES;
        ldfrags(0, 0, sbase);
        int cur = 0;
#pragma unroll
        for (int k16 = 0; k16 < 4; k16++) {
            if (k16 < 3) ldfrags(k16 + 1, cur ^ 1, sbase);
            if (k16 == 3) {
                __syncthreads();
                if (i + 3 < nch) load_chunk(i + 3, s);
            }
#pragma unroll
            for (int p = 0; p < 3; p++) {
#pragma unroll
                for (int mt = 0; mt < 4; mt++) {
                    const uint32_t* af = (p == 2) ? alf[cur][mt] : ahf[cur][mt];
#pragma unroll
                    for (int nt = 0; nt < 4; nt++) {
                        const uint32_t* bf = (p == 1) ? &blf[cur][nt >> 1][(nt & 1) * 2]
                                                      : &bhf[cur][nt >> 1][(nt & 1) * 2];
                        mma16816(acc[mt][nt], af, bf);
                    }
                }
            }
            cur ^= 1;
        }
    }

    const int er = lid >> 2;
    const int ec = (lid & 3) * 2;
#pragma unroll
    for (int mt = 0; mt < 4; mt++) {
#pragma unroll
        for (int nt = 0; nt < 4; nt++) {
            const long long row0 = m0 + wm + mt * 16 + er;
            const long long col  = n0 + wn + nt * 8 + ec;
            if (mode == 0) {
                float2 v0, v1;
                v0.x = acc[mt][nt][0] * alpha; v0.y = acc[mt][nt][1] * alpha;
                v1.x = acc[mt][nt][2] * alpha; v1.y = acc[mt][nt][3] * alpha;
                *(float2*)(Df + (long long)b * sD + row0 * N + col)       = v0;
                *(float2*)(Df + (long long)b * sD + (row0 + 8) * N + col) = v1;
            } else {
                float p0 = acc[mt][nt][0] * alpha, p1 = acc[mt][nt][1] * alpha;
                float p2 = acc[mt][nt][2] * alpha, p3 = acc[mt][nt][3] * alpha;
                __nv_bfloat16 h0, h1, h2, h3, l0, l1, l2, l3;
                split_bf16(p0, h0, l0); split_bf16(p1, h1, l1);
                split_bf16(p2, h2, l2); split_bf16(p3, h3, l3);
                long long base = (long long)b * sD;
                *(__nv_bfloat162*)(Dh + base + row0 * N + col)       = __nv_bfloat162(h0, h1);
                *(__nv_bfloat162*)(Dh + base + (row0 + 8) * N + col) = __nv_bfloat162(h2, h3);
                *(__nv_bfloat162*)(Dl + base + row0 * N + col)       = __nv_bfloat162(l0, l1);
                *(__nv_bfloat162*)(Dl + base + (row0 + 8) * N + col) = __nv_bfloat162(l2, l3);
            }
        }
    }
}

// ============================================================================
// SYRK: C = x^T x, upper-triangle blocks only. x [S,F]; trans-ldmatrix frags.
// ============================================================================
__global__ void __launch_bounds__(256, 1)
syrk_bf16x3(const __nv_bfloat16* __restrict__ xh, const __nv_bfloat16* __restrict__ xl,
            __nv_bfloat16* __restrict__ Ch, __nv_bfloat16* __restrict__ Cl)
{
    extern __shared__ char smem[];
    int t = blockIdx.x, by = 0;
    while (t >= 8 - by) { t -= 8 - by; by++; }
    const int bx = by + t;
    const bool diag = (bx == by);

    const int b = blockIdx.z;
    const long long xoff = (long long)b * NSEQ * FDIM;
    const int m0 = by * 128, n0 = bx * 128;
    const int tid = (int)threadIdx.x;
    const int wid = tid >> 5;
    const int lid = tid & 31;
    const int wm = (wid >> 2) * 64;
    const int wn = (wid & 3) * 32;

    const uint32_t sb = smem_u32(smem);
    const uint32_t offBH = diag ? OFF_AH : OFF_BH;
    const uint32_t offBL = offBH + 16384;

    auto load_chunk = [&](int kc, int stage) {
        const uint32_t sbase = sb + stage * STAGE_BYTES;
        const long long s0 = (long long)kc * 64;
#pragma unroll
        for (int j = 0; j < 4; j++) {
            int idx = j * 256 + tid;
            int r   = idx >> 4;
            int cb  = (idx & 15) << 4;
            uint32_t sw = (uint32_t)(r * 256 + cb) ^ (uint32_t)((r & 7) << 4);
            long long g = xoff + (s0 + r) * FDIM;
            cp16(sbase + OFF_AH + sw, xh + g + m0 + (cb >> 1));
            cp16(sbase + OFF_AL + sw, xl + g + m0 + (cb >> 1));
            if (!diag) {
                cp16(sbase + OFF_BH + sw, xh + g + n0 + (cb >> 1));
                cp16(sbase + OFF_BL + sw, xl + g + n0 + (cb >> 1));
            }
        }
        CP_COMMIT();
    };

    float acc[4][4][4];
#pragma unroll
    for (int i = 0; i < 4; i++)
#pragma unroll
        for (int j = 0; j < 4; j++)
#pragma unroll
            for (int c = 0; c < 4; c++) acc[i][j][c] = 0.0f;

    const int a_krow  = ((lid >> 4) & 1) * 8 + (lid & 7);
    const int a_mbyte = ((lid >> 3) & 1) * 16;
    const int b_krow  = ((lid >> 3) & 1) * 8 + (lid & 7);
    const int b_nbyte = ((lid >> 4) & 1) * 16;

    uint32_t ahf[2][4][4], alf[2][4][4], bhf[2][2][4], blf[2][2][4];

    auto ldfrags = [&](int k16, int buf, uint32_t sbase) {
#pragma unroll
        for (int mt = 0; mt < 4; mt++) {
            uint32_t off = (uint32_t)((k16 * 16 + a_krow) * 256 + (wm + mt * 16) * 2 + a_mbyte);
            off ^= (uint32_t)((a_krow & 7) << 4);
            ldsm4t(ahf[buf][mt], sbase + OFF_AH + off);
            ldsm4t(alf[buf][mt], sbase + OFF_AL + off);
        }
#pragma unroll
        for (int np = 0; np < 2; np++) {
            uint32_t off = (uint32_t)((k16 * 16 + b_krow) * 256 + (wn + np * 16) * 2 + b_nbyte);
            off ^= (uint32_t)((b_krow & 7) << 4);
            ldsm4t(bhf[buf][np], sbase + offBH + off);
            ldsm4t(blf[buf][np], sbase + offBL + off);
        }
    };

    const int nch = NSEQ >> 6;   // 64
    load_chunk(0, 0);
    load_chunk(1, 1);
    load_chunk(2, 2);

    for (int i = 0; i < nch; i++) {
        const int s = i % 3;
        const int rem = nch - 1 - i;
        if (rem >= 2)      { CP_WAIT2(); }
        else if (rem == 1) { CP_WAIT1(); }
        else               { CP_WAIT0(); }
        __syncthreads();

        const uint32_t sbase = sb + s * STAGE_BYTES;
        ldfrags(0, 0, sbase);
        int cur = 0;
#pragma unroll
        for (int k16 = 0; k16 < 4; k16++) {
            if (k16 < 3) ldfrags(k16 + 1, cur ^ 1, sbase);
            if (k16 == 3) {
                __syncthreads();
                if (i + 3 < nch) load_chunk(i + 3, s);
            }
#pragma unroll
            for (int p = 0; p < 3; p++) {
#pragma unroll
                for (int mt = 0; mt < 4; mt++) {
                    const uint32_t* af = (p == 2) ? alf[cur][mt] : ahf[cur][mt];
#pragma unroll
                    for (int nt = 0; nt < 4; nt++) {
                        const uint32_t* bf = (p == 1) ? &blf[cur][nt >> 1][(nt & 1) * 2]
                                                      : &bhf[cur][nt >> 1][(nt & 1) * 2];
                        mma16816(acc[mt][nt], af, bf);
                    }
                }
            }
            cur ^= 1;
        }
    }

    const int er = lid >> 2;
    const int ec = (lid & 3) * 2;
    const long long base = (long long)b * FDIM * FDIM;
#pragma unroll
    for (int mt = 0; mt < 4; mt++) {
#pragma unroll
        for (int nt = 0; nt < 4; nt++) {
            const long long row0 = m0 + wm + mt * 16 + er;
            const long long col  = n0 + wn + nt * 8 + ec;
            float p0 = acc[mt][nt][0], p1 = acc[mt][nt][1];
            float p2 = acc[mt][nt][2], p3 = acc[mt][nt][3];
            __nv_bfloat16 h0, h1, h2, h3, l0, l1, l2, l3;
            split_bf16(p0, h0, l0); split_bf16(p1, h1, l1);
            split_bf16(p2, h2, l2); split_bf16(p3, h3, l3);
            *(__nv_bfloat162*)(Ch + base + row0 * FDIM + col)       = __nv_bfloat162(h0, h1);
            *(__nv_bfloat162*)(Ch + base + (row0 + 8) * FDIM + col) = __nv_bfloat162(h2, h3);
            *(__nv_bfloat162*)(Cl + base + row0 * FDIM + col)       = __nv_bfloat162(l0, l1);
            *(__nv_bfloat162*)(Cl + base + (row0 + 8) * FDIM + col) = __nv_bfloat162(l2, l3);
        }
    }
}

// ============================================================================
// Mirror upper triangle of C into lower triangle (hi and lo).
// ============================================================================
__global__ void mirror_kernel(__nv_bfloat16* __restrict__ Ch, __nv_bfloat16* __restrict__ Cl)
{
    int t = blockIdx.x, ty = 0;
    while (t >= 32 - ty) { t -= 32 - ty; ty++; }
    const int tx = ty + t;
    const int b = blockIdx.y;
    const long long base = (long long)b * FDIM * FDIM;
    __shared__ __nv_bfloat16 sh[32][33];
    __shared__ __nv_bfloat16 sl[32][33];
    const int x_ = threadIdx.x, y = threadIdx.y;
    const int r0 = ty * 32, c0 = tx * 32;
#pragma unroll
    for (int r = 0; r < 4; r++) {
        int i = r0 + y + r * 8;
        sh[y + r * 8][x_] = Ch[base + (long long)i * FDIM + c0 + x_];
        sl[y + r * 8][x_] = Cl[base + (long long)i * FDIM + c0 + x_];
    }
    __syncthreads();
#pragma unroll
    for (int r = 0; r < 4; r++) {
        int j = c0 + y + r * 8;
        int i = r0 + x_;
        if (j > i) {
            Ch[base + (long long)j * FDIM + i] = sh[x_][y + r * 8];
            Cl[base + (long long)j * FDIM + i] = sl[x_][y + r * 8];
        }
    }
}

// ---------------- conversion kernels ----------------
__global__ void conv_x_kernel(const float4* __restrict__ x,
                              __nv_bfloat162* __restrict__ xh2, __nv_bfloat162* __restrict__ xl2)
{
    const int i = blockIdx.x * blockDim.x + threadIdx.x;
#pragma unroll
    for (int p = 0; p < 2; p++) {
        float4 v = x[i * 2 + p];
        __nv_bfloat16 h0, h1, h2, h3, l0, l1, l2, l3;
        split_bf16(v.x, h0, l0); split_bf16(v.y, h1, l1);
        split_bf16(v.z, h2, l2); split_bf16(v.w, h3, l3);
        xh2[i * 4 + p * 2 + 0] = __nv_bfloat162(h0, h1);
        xh2[i * 4 + p * 2 + 1] = __nv_bfloat162(h2, h3);
        xl2[i * 4 + p * 2 + 0] = __nv_bfloat162(l0, l1);
        xl2[i * 4 + p * 2 + 1] = __nv_bfloat162(l2, l3);
    }
}

__global__ void conv_pair_kernel(const float* __restrict__ in,
                                 __nv_bfloat16* __restrict__ oh, __nv_bfloat16* __restrict__ ol, int n)
{
    int i = blockIdx.x * blockDim.x + threadIdx.x;
    if (i < n) {
        __nv_bfloat16 h, l; split_bf16(in[i], h, l);
        oh[i] = h; ol[i] = l;
    }
}

// ---------------- launcher ----------------
extern "C" void kernel_launch(void* const* d_in, const int* in_sizes, int n_in,
                              void* d_out, int out_size)
{
    const float* x  = (const float*)d_in[0];   // [8,4096,1024]
    const float* Wt = (const float*)d_in[1];   // [256,1024]
    const float* Wp = (const float*)d_in[2];   // [256,1024]
    const float* Wg = (const float*)d_in[3];   // [1024,1024]
    float* out = (float*)d_out;                // [8,4096,1024]

    __nv_bfloat16 *xh, *xl, *Th, *Tl, *Ch, *Cl, *Ph, *Pl, *Qh, *Ql;
    __nv_bfloat16 *Wth, *Wtl, *Wph, *Wpl, *Wgh, *Wgl;
    cudaGetSymbolAddress((void**)&xh, g_xh);   cudaGetSymbolAddress((void**)&xl, g_xl);
    cudaGetSymbolAddress((void**)&Th, g_Th);   cudaGetSymbolAddress((void**)&Tl, g_Tl);
    cudaGetSymbolAddress((void**)&Ch, g_Ch);   cudaGetSymbolAddress((void**)&Cl, g_Cl);
    cudaGetSymbolAddress((void**)&Ph, g_Ph);   cudaGetSymbolAddress((void**)&Pl, g_Pl);
    cudaGetSymbolAddress((void**)&Qh, g_Qh);   cudaGetSymbolAddress((void**)&Ql, g_Ql);
    cudaGetSymbolAddress((void**)&Wth, g_Wth); cudaGetSymbolAddress((void**)&Wtl, g_Wtl);
    cudaGetSymbolAddress((void**)&Wph, g_Wph); cudaGetSymbolAddress((void**)&Wpl, g_Wpl);
    cudaGetSymbolAddress((void**)&Wgh, g_Wgh); cudaGetSymbolAddress((void**)&Wgl, g_Wgl);

    cudaFuncSetAttribute(gemm_bf16x3, cudaFuncAttributeMaxDynamicSharedMemorySize, GEMM_SMEM);
    cudaFuncSetAttribute(syrk_bf16x3, cudaFuncAttributeMaxDynamicSharedMemorySize, GEMM_SMEM);

    const float scale = 1.0f / 32.0f;  // 1/sqrt(1024)

    // ---- conversions (indices 0..3) ----
    const int nx = BATCH * NSEQ * FDIM;
    conv_x_kernel<<<nx / 8 / 256, 256>>>((const float4*)x, (__nv_bfloat162*)xh, (__nv_bfloat162*)xl);
    conv_pair_kernel<<<(LDIM * FDIM) / 256, 256>>>(Wt, Wth, Wtl, LDIM * FDIM);
    conv_pair_kernel<<<(LDIM * FDIM) / 256, 256>>>(Wp, Wph, Wpl, LDIM * FDIM);
    conv_pair_kernel<<<(ODIM * FDIM) / 256, 256>>>(Wg, Wgh, Wgl, ODIM * FDIM);

    const long long sX = (long long)NSEQ * FDIM;
    const long long sT = (long long)NSEQ * LDIM;
    const long long sC = (long long)FDIM * FDIM;
    const long long sP = (long long)LDIM * FDIM;
    const long long sQ = (long long)ODIM * LDIM;

    // ---- (index 4) theta = x @ Wtheta^T : M=4096, N=256, K=1024 ----
    gemm_bf16x3<<<dim3(LDIM / 128, NSEQ / 128, BATCH), 256, GEMM_SMEM>>>(
        xh, xl, Wth, Wtl, nullptr, Th, Tl, LDIM, FDIM, sX, 0, sT, 1.0f, 1);

    // ---- (index 5: ncu target) C = x^T x, upper-triangle blocks ----
    syrk_bf16x3<<<dim3(36, 1, BATCH), 256, GEMM_SMEM>>>(xh, xl, Ch, Cl);
    mirror_kernel<<<dim3(528, BATCH), dim3(32, 8)>>>(Ch, Cl);

    // ---- P = scale * Wphi @ C : M=256, N=1024, K=1024 ----
    gemm_bf16x3<<<dim3(8, 2, BATCH), 256, GEMM_SMEM>>>(
        Wph, Wpl, Ch, Cl, nullptr, Ph, Pl, FDIM, FDIM, 0, sC, sP, scale, 1);

    // ---- QT[o,l] = sum_f Wg[o,f] P[l,f] : M=1024, N=256, K=1024 ----
    gemm_bf16x3<<<dim3(2, 8, BATCH), 256, GEMM_SMEM>>>(
        Wgh, Wgl, Ph, Pl, nullptr, Qh, Ql, LDIM, FDIM, 0, sP, sQ, 1.0f, 1);

    // ---- out[s,o] = sum_l theta[s,l] QT[o,l] : M=4096, N=1024, K=256 ----
    gemm_bf16x3<<<dim3(ODIM / 128, NSEQ / 128, BATCH), 256, GEMM_SMEM>>>(
        Th, Tl, Qh, Ql, out, nullptr, nullptr, ODIM, LDIM, sT, sQ, sX, 1.0f, 0);
}

// round 7
// speedup vs baseline: 5.7766x; 1.0788x over previous
#include <cuda_runtime.h>
#include <cuda_bf16.h>
#include <math.h>
#include <stdint.h>

// ---------------- problem constants ----------------
#define BATCH 8
#define NSEQ  4096
#define FDIM  1024
#define LDIM  256
#define ODIM  1024

// ---------------- scratch (device globals) ----------------
__device__ __nv_bfloat16 g_xh [BATCH * NSEQ * FDIM];
__device__ __nv_bfloat16 g_xl [BATCH * NSEQ * FDIM];
__device__ __nv_bfloat16 g_Th [BATCH * NSEQ * LDIM];
__device__ __nv_bfloat16 g_Tl [BATCH * NSEQ * LDIM];
__device__ __nv_bfloat16 g_Ch [BATCH * FDIM * FDIM];
__device__ __nv_bfloat16 g_Cl [BATCH * FDIM * FDIM];
__device__ __nv_bfloat16 g_Ph [BATCH * LDIM * FDIM];
__device__ __nv_bfloat16 g_Pl [BATCH * LDIM * FDIM];
__device__ __nv_bfloat16 g_Qh [BATCH * ODIM * LDIM];
__device__ __nv_bfloat16 g_Ql [BATCH * ODIM * LDIM];
__device__ __nv_bfloat16 g_Wth[LDIM * FDIM];
__device__ __nv_bfloat16 g_Wtl[LDIM * FDIM];
__device__ __nv_bfloat16 g_Wph[LDIM * FDIM];
__device__ __nv_bfloat16 g_Wpl[LDIM * FDIM];
__device__ __nv_bfloat16 g_Wgh[ODIM * FDIM];
__device__ __nv_bfloat16 g_Wgl[ODIM * FDIM];

// ---------------- PTX helpers ----------------
__device__ __forceinline__ uint32_t smem_u32(const void* p) {
    uint32_t a;
    asm("{ .reg .u64 t; cvta.to.shared.u64 t, %1; cvt.u32.u64 %0, t; }" : "=r"(a) : "l"(p));
    return a;
}
__device__ __forceinline__ void cp16(uint32_t dst, const void* src) {
    asm volatile("cp.async.cg.shared.global [%0], [%1], 16;\n" :: "r"(dst), "l"(src));
}
#define CP_COMMIT()  asm volatile("cp.async.commit_group;\n" ::: "memory")
#define CP_WAIT0()   asm volatile("cp.async.wait_group 0;\n" ::: "memory")
#define CP_WAIT1()   asm volatile("cp.async.wait_group 1;\n" ::: "memory")
#define CP_WAIT2()   asm volatile("cp.async.wait_group 2;\n" ::: "memory")

__device__ __forceinline__ void ldsm4(uint32_t* r, uint32_t addr) {
    asm volatile("ldmatrix.sync.aligned.m8n8.x4.shared.b16 {%0,%1,%2,%3}, [%4];"
        : "=r"(r[0]), "=r"(r[1]), "=r"(r[2]), "=r"(r[3]) : "r"(addr));
}
__device__ __forceinline__ void ldsm4t(uint32_t* r, uint32_t addr) {
    asm volatile("ldmatrix.sync.aligned.m8n8.x4.trans.shared.b16 {%0,%1,%2,%3}, [%4];"
        : "=r"(r[0]), "=r"(r[1]), "=r"(r[2]), "=r"(r[3]) : "r"(addr));
}
__device__ __forceinline__ void mma16816(float* d, const uint32_t* a, const uint32_t* b) {
    asm volatile(
        "mma.sync.aligned.m16n8k16.row.col.f32.bf16.bf16.f32 "
        "{%0,%1,%2,%3}, {%4,%5,%6,%7}, {%8,%9}, {%0,%1,%2,%3};"
        : "+f"(d[0]), "+f"(d[1]), "+f"(d[2]), "+f"(d[3])
        : "r"(a[0]), "r"(a[1]), "r"(a[2]), "r"(a[3]), "r"(b[0]), "r"(b[1]));
}
__device__ __forceinline__ uint32_t sw128(uint32_t off) {
    return off ^ ((off >> 3) & 0x70);
}
__device__ __forceinline__ void split_bf16(float v, __nv_bfloat16& h, __nv_bfloat16& l) {
    h = __float2bfloat16(v);
    l = __float2bfloat16(v - __bfloat162float(h));
}

// smem: 3 stages x 64KB. Stage: Ah | Al | Bh | Bl (16KB each)
#define STAGE_BYTES 65536
#define OFF_AH 0
#define OFF_AL 16384
#define OFF_BH 32768
#define OFF_BL 49152
#define GEMM_SMEM (3 * STAGE_BYTES)

// ============================================================================
// Generic HMMA GEMM: D[m,n] = alpha * sum_k A[m,k]*B[n,k]  (bf16x3, batched)
// ============================================================================
__global__ void __launch_bounds__(256, 1)
gemm_bf16x3(const __nv_bfloat16* __restrict__ Ah, const __nv_bfloat16* __restrict__ Al,
            const __nv_bfloat16* __restrict__ Bh, const __nv_bfloat16* __restrict__ Bl,
            float* __restrict__ Df, __nv_bfloat16* __restrict__ Dh, __nv_bfloat16* __restrict__ Dl,
            int N, int K,
            long long sA, long long sB, long long sD,
            float alpha, int mode)
{
    extern __shared__ char smem[];
    const int b = blockIdx.z;
    Ah += (long long)b * sA;  Al += (long long)b * sA;
    Bh += (long long)b * sB;  Bl += (long long)b * sB;

    const int m0 = blockIdx.y * 128;
    const int n0 = blockIdx.x * 128;
    const int tid = (int)threadIdx.x;
    const int wid = tid >> 5;
    const int lid = tid & 31;
    const int wm = (wid >> 2) * 64;
    const int wn = (wid & 3) * 32;

    const uint32_t sb = smem_u32(smem);
    const int nch = K >> 6;

    auto load_chunk = [&](int kc, int stage) {
        const long long kofs = (long long)kc * 64;
        const uint32_t sbase = sb + stage * STAGE_BYTES;
#pragma unroll
        for (int j = 0; j < 4; j++) {
            int idx = j * 256 + tid;
            int r   = idx >> 3;
            int cb  = (idx & 7) << 4;
            uint32_t sw = sw128((uint32_t)(r * 128 + cb));
            long long ea = (long long)(m0 + r) * K + kofs + (cb >> 1);
            long long eb = (long long)(n0 + r) * K + kofs + (cb >> 1);
            cp16(sbase + OFF_AH + sw, Ah + ea);
            cp16(sbase + OFF_AL + sw, Al + ea);
            cp16(sbase + OFF_BH + sw, Bh + eb);
            cp16(sbase + OFF_BL + sw, Bl + eb);
        }
        CP_COMMIT();
    };

    float acc[4][4][4];
#pragma unroll
    for (int i = 0; i < 4; i++)
#pragma unroll
        for (int j = 0; j < 4; j++)
#pragma unroll
            for (int c = 0; c < 4; c++) acc[i][j][c] = 0.0f;

    const int a_row = wm + (lid & 15);
    const int a_cb  = (lid >> 4) * 16;
    const int b_row = wn + (lid & 7) + ((lid >> 4) & 1) * 8;
    const int b_cb  = ((lid >> 3) & 1) * 16;

    uint32_t ahf[2][4][4], alf[2][4][4], bhf[2][2][4], blf[2][2][4];

    auto ldfrags = [&](int k16, int buf, uint32_t sbase) {
        const int kb = k16 * 32;
#pragma unroll
        for (int mt = 0; mt < 4; mt++) {
            uint32_t sw = sw128((uint32_t)((a_row + mt * 16) * 128 + kb + a_cb));
            ldsm4(ahf[buf][mt], sbase + OFF_AH + sw);
            ldsm4(alf[buf][mt], sbase + OFF_AL + sw);
        }
#pragma unroll
        for (int np = 0; np < 2; np++) {
            uint32_t sw = sw128((uint32_t)((b_row + np * 16) * 128 + kb + b_cb));
            ldsm4(bhf[buf][np], sbase + OFF_BH + sw);
            ldsm4(blf[buf][np], sbase + OFF_BL + sw);
        }
    };

    load_chunk(0, 0);
    if (nch > 1) load_chunk(1, 1);
    if (nch > 2) load_chunk(2, 2);

    for (int i = 0; i < nch; i++) {
        const int s = i % 3;
        const int rem = nch - 1 - i;
        if (rem >= 2)      { CP_WAIT2(); }
        else if (rem == 1) { CP_WAIT1(); }
        else               { CP_WAIT0(); }
        __syncthreads();

        const uint32_t sbase = sb + s * STAGE_BYTES;
        ldfrags(0, 0, sbase);
        int cur = 0;
#pragma unroll
        for (int k16 = 0; k16 < 4; k16++) {
            if (k16 < 3) ldfrags(k16 + 1, cur ^ 1, sbase);
            if (k16 == 3) {
                __syncthreads();
                if (i + 3 < nch) load_chunk(i + 3, s);
            }
#pragma unroll
            for (int p = 0; p < 3; p++) {
#pragma unroll
                for (int mt = 0; mt < 4; mt++) {
                    const uint32_t* af = (p == 2) ? alf[cur][mt] : ahf[cur][mt];
#pragma unroll
                    for (int nt = 0; nt < 4; nt++) {
                        const uint32_t* bf = (p == 1) ? &blf[cur][nt >> 1][(nt & 1) * 2]
                                                      : &bhf[cur][nt >> 1][(nt & 1) * 2];
                        mma16816(acc[mt][nt], af, bf);
                    }
                }
            }
            cur ^= 1;
        }
    }

    const int er = lid >> 2;
    const int ec = (lid & 3) * 2;
#pragma unroll
    for (int mt = 0; mt < 4; mt++) {
#pragma unroll
        for (int nt = 0; nt < 4; nt++) {
            const long long row0 = m0 + wm + mt * 16 + er;
            const long long col  = n0 + wn + nt * 8 + ec;
            if (mode == 0) {
                float2 v0, v1;
                v0.x = acc[mt][nt][0] * alpha; v0.y = acc[mt][nt][1] * alpha;
                v1.x = acc[mt][nt][2] * alpha; v1.y = acc[mt][nt][3] * alpha;
                *(float2*)(Df + (long long)b * sD + row0 * N + col)       = v0;
                *(float2*)(Df + (long long)b * sD + (row0 + 8) * N + col) = v1;
            } else {
                float p0 = acc[mt][nt][0] * alpha, p1 = acc[mt][nt][1] * alpha;
                float p2 = acc[mt][nt][2] * alpha, p3 = acc[mt][nt][3] * alpha;
                __nv_bfloat16 h0, h1, h2, h3, l0, l1, l2, l3;
                split_bf16(p0, h0, l0); split_bf16(p1, h1, l1);
                split_bf16(p2, h2, l2); split_bf16(p3, h3, l3);
                long long base = (long long)b * sD;
                *(__nv_bfloat162*)(Dh + base + row0 * N + col)       = __nv_bfloat162(h0, h1);
                *(__nv_bfloat162*)(Dh + base + (row0 + 8) * N + col) = __nv_bfloat162(h2, h3);
                *(__nv_bfloat162*)(Dl + base + row0 * N + col)       = __nv_bfloat162(l0, l1);
                *(__nv_bfloat162*)(Dl + base + (row0 + 8) * N + col) = __nv_bfloat162(l2, l3);
            }
        }
    }
}

// ============================================================================
// SYRK: C = x^T x, upper-triangle blocks only.
// ============================================================================
__global__ void __launch_bounds__(256, 1)
syrk_bf16x3(const __nv_bfloat16* __restrict__ xh, const __nv_bfloat16* __restrict__ xl,
            __nv_bfloat16* __restrict__ Ch, __nv_bfloat16* __restrict__ Cl)
{
    extern __shared__ char smem[];
    int t = blockIdx.x, by = 0;
    while (t >= 8 - by) { t -= 8 - by; by++; }
    const int bx = by + t;
    const bool diag = (bx == by);

    const int b = blockIdx.z;
    const long long xoff = (long long)b * NSEQ * FDIM;
    const int m0 = by * 128, n0 = bx * 128;
    const int tid = (int)threadIdx.x;
    const int wid = tid >> 5;
    const int lid = tid & 31;
    const int wm = (wid >> 2) * 64;
    const int wn = (wid & 3) * 32;

    const uint32_t sb = smem_u32(smem);
    const uint32_t offBH = diag ? OFF_AH : OFF_BH;
    const uint32_t offBL = offBH + 16384;

    auto load_chunk = [&](int kc, int stage) {
        const uint32_t sbase = sb + stage * STAGE_BYTES;
        const long long s0 = (long long)kc * 64;
#pragma unroll
        for (int j = 0; j < 4; j++) {
            int idx = j * 256 + tid;
            int r   = idx >> 4;
            int cb  = (idx & 15) << 4;
            uint32_t sw = (uint32_t)(r * 256 + cb) ^ (uint32_t)((r & 7) << 4);
            long long g = xoff + (s0 + r) * FDIM;
            cp16(sbase + OFF_AH + sw, xh + g + m0 + (cb >> 1));
            cp16(sbase + OFF_AL + sw, xl + g + m0 + (cb >> 1));
            if (!diag) {
                cp16(sbase + OFF_BH + sw, xh + g + n0 + (cb >> 1));
                cp16(sbase + OFF_BL + sw, xl + g + n0 + (cb >> 1));
            }
        }
        CP_COMMIT();
    };

    float acc[4][4][4];
#pragma unroll
    for (int i = 0; i < 4; i++)
#pragma unroll
        for (int j = 0; j < 4; j++)
#pragma unroll
            for (int c = 0; c < 4; c++) acc[i][j][c] = 0.0f;

    const int a_krow  = ((lid >> 4) & 1) * 8 + (lid & 7);
    const int a_mbyte = ((lid >> 3) & 1) * 16;
    const int b_krow  = ((lid >> 3) & 1) * 8 + (lid & 7);
    const int b_nbyte = ((lid >> 4) & 1) * 16;

    uint32_t ahf[2][4][4], alf[2][4][4], bhf[2][2][4], blf[2][2][4];

    auto ldfrags = [&](int k16, int buf, uint32_t sbase) {
#pragma unroll
        for (int mt = 0; mt < 4; mt++) {
            uint32_t off = (uint32_t)((k16 * 16 + a_krow) * 256 + (wm + mt * 16) * 2 + a_mbyte);
            off ^= (uint32_t)((a_krow & 7) << 4);
            ldsm4t(ahf[buf][mt], sbase + OFF_AH + off);
            ldsm4t(alf[buf][mt], sbase + OFF_AL + off);
        }
#pragma unroll
        for (int np = 0; np < 2; np++) {
            uint32_t off = (uint32_t)((k16 * 16 + b_krow) * 256 + (wn + np * 16) * 2 + b_nbyte);
            off ^= (uint32_t)((b_krow & 7) << 4);
            ldsm4t(bhf[buf][np], sbase + offBH + off);
            ldsm4t(blf[buf][np], sbase + offBL + off);
        }
    };

    const int nch = NSEQ >> 6;
    load_chunk(0, 0);
    load_chunk(1, 1);
    load_chunk(2, 2);

    for (int i = 0; i < nch; i++) {
        const int s = i % 3;
        const int rem = nch - 1 - i;
        if (rem >= 2)      { CP_WAIT2(); }
        else if (rem == 1) { CP_WAIT1(); }
        else               { CP_WAIT0(); }
        __syncthreads();

        const uint32_t sbase = sb + s * STAGE_BYTES;
        ldfrags(0, 0, sbase);
        int cur = 0;
#pragma unroll
        for (int k16 = 0; k16 < 4; k16++) {
            if (k16 < 3) ldfrags(k16 + 1, cur ^ 1, sbase);
            if (k16 == 3) {
                __syncthreads();
                if (i + 3 < nch) load_chunk(i + 3, s);
            }
#pragma unroll
            for (int p = 0; p < 3; p++) {
#pragma unroll
                for (int mt = 0; mt < 4; mt++) {
                    const uint32_t* af = (p == 2) ? alf[cur][mt] : ahf[cur][mt];
#pragma unroll
                    for (int nt = 0; nt < 4; nt++) {
                        const uint32_t* bf = (p == 1) ? &blf[cur][nt >> 1][(nt & 1) * 2]
                                                      : &bhf[cur][nt >> 1][(nt & 1) * 2];
                        mma16816(acc[mt][nt], af, bf);
                    }
                }
            }
            cur ^= 1;
        }
    }

    const int er = lid >> 2;
    const int ec = (lid & 3) * 2;
    const long long base = (long long)b * FDIM * FDIM;
#pragma unroll
    for (int mt = 0; mt < 4; mt++) {
#pragma unroll
        for (int nt = 0; nt < 4; nt++) {
            const long long row0 = m0 + wm + mt * 16 + er;
            const long long col  = n0 + wn + nt * 8 + ec;
            float p0 = acc[mt][nt][0], p1 = acc[mt][nt][1];
            float p2 = acc[mt][nt][2], p3 = acc[mt][nt][3];
            __nv_bfloat16 h0, h1, h2, h3, l0, l1, l2, l3;
            split_bf16(p0, h0, l0); split_bf16(p1, h1, l1);
            split_bf16(p2, h2, l2); split_bf16(p3, h3, l3);
            *(__nv_bfloat162*)(Ch + base + row0 * FDIM + col)       = __nv_bfloat162(h0, h1);
            *(__nv_bfloat162*)(Ch + base + (row0 + 8) * FDIM + col) = __nv_bfloat162(h2, h3);
            *(__nv_bfloat162*)(Cl + base + row0 * FDIM + col)       = __nv_bfloat162(l0, l1);
            *(__nv_bfloat162*)(Cl + base + (row0 + 8) * FDIM + col) = __nv_bfloat162(l2, l3);
        }
    }
}

// ============================================================================
// Mirror upper triangle of C into lower triangle (hi and lo).
// ============================================================================
__global__ void mirror_kernel(__nv_bfloat16* __restrict__ Ch, __nv_bfloat16* __restrict__ Cl)
{
    int t = blockIdx.x, ty = 0;
    while (t >= 32 - ty) { t -= 32 - ty; ty++; }
    const int tx = ty + t;
    const int b = blockIdx.y;
    const long long base = (long long)b * FDIM * FDIM;
    __shared__ __nv_bfloat16 sh[32][33];
    __shared__ __nv_bfloat16 sl[32][33];
    const int x_ = threadIdx.x, y = threadIdx.y;
    const int r0 = ty * 32, c0 = tx * 32;
#pragma unroll
    for (int r = 0; r < 4; r++) {
        int i = r0 + y + r * 8;
        sh[y + r * 8][x_] = Ch[base + (long long)i * FDIM + c0 + x_];
        sl[y + r * 8][x_] = Cl[base + (long long)i * FDIM + c0 + x_];
    }
    __syncthreads();
#pragma unroll
    for (int r = 0; r < 4; r++) {
        int j = c0 + y + r * 8;
        int i = r0 + x_;
        if (j > i) {
            Ch[base + (long long)j * FDIM + i] = sh[x_][y + r * 8];
            Cl[base + (long long)j * FDIM + i] = sl[x_][y + r * 8];
        }
    }
}

// ---------------- conversion kernels ----------------
__global__ void conv_x_kernel(const float4* __restrict__ x,
                              __nv_bfloat162* __restrict__ xh2, __nv_bfloat162* __restrict__ xl2)
{
    const int i = blockIdx.x * blockDim.x + threadIdx.x;
#pragma unroll
    for (int p = 0; p < 2; p++) {
        float4 v = x[i * 2 + p];
        __nv_bfloat16 h0, h1, h2, h3, l0, l1, l2, l3;
        split_bf16(v.x, h0, l0); split_bf16(v.y, h1, l1);
        split_bf16(v.z, h2, l2); split_bf16(v.w, h3, l3);
        xh2[i * 4 + p * 2 + 0] = __nv_bfloat162(h0, h1);
        xh2[i * 4 + p * 2 + 1] = __nv_bfloat162(h2, h3);
        xl2[i * 4 + p * 2 + 0] = __nv_bfloat162(l0, l1);
        xl2[i * 4 + p * 2 + 1] = __nv_bfloat162(l2, l3);
    }
}

__global__ void conv_pair_kernel(const float* __restrict__ in,
                                 __nv_bfloat16* __restrict__ oh, __nv_bfloat16* __restrict__ ol, int n)
{
    int i = blockIdx.x * blockDim.x + threadIdx.x;
    if (i < n) {
        __nv_bfloat16 h, l; split_bf16(in[i], h, l);
        oh[i] = h; ol[i] = l;
    }
}

// ---------------- launcher (two-stream overlap) ----------------
extern "C" void kernel_launch(void* const* d_in, const int* in_sizes, int n_in,
                              void* d_out, int out_size)
{
    const float* x  = (const float*)d_in[0];
    const float* Wt = (const float*)d_in[1];
    const float* Wp = (const float*)d_in[2];
    const float* Wg = (const float*)d_in[3];
    float* out = (float*)d_out;

    __nv_bfloat16 *xh, *xl, *Th, *Tl, *Ch, *Cl, *Ph, *Pl, *Qh, *Ql;
    __nv_bfloat16 *Wth, *Wtl, *Wph, *Wpl, *Wgh, *Wgl;
    cudaGetSymbolAddress((void**)&xh, g_xh);   cudaGetSymbolAddress((void**)&xl, g_xl);
    cudaGetSymbolAddress((void**)&Th, g_Th);   cudaGetSymbolAddress((void**)&Tl, g_Tl);
    cudaGetSymbolAddress((void**)&Ch, g_Ch);   cudaGetSymbolAddress((void**)&Cl, g_Cl);
    cudaGetSymbolAddress((void**)&Ph, g_Ph);   cudaGetSymbolAddress((void**)&Pl, g_Pl);
    cudaGetSymbolAddress((void**)&Qh, g_Qh);   cudaGetSymbolAddress((void**)&Ql, g_Ql);
    cudaGetSymbolAddress((void**)&Wth, g_Wth); cudaGetSymbolAddress((void**)&Wtl, g_Wtl);
    cudaGetSymbolAddress((void**)&Wph, g_Wph); cudaGetSymbolAddress((void**)&Wpl, g_Wpl);
    cudaGetSymbolAddress((void**)&Wgh, g_Wgh); cudaGetSymbolAddress((void**)&Wgl, g_Wgl);

    cudaFuncSetAttribute(gemm_bf16x3, cudaFuncAttributeMaxDynamicSharedMemorySize, GEMM_SMEM);
    cudaFuncSetAttribute(syrk_bf16x3, cudaFuncAttributeMaxDynamicSharedMemorySize, GEMM_SMEM);

    // one-time stream/event resources (no device-memory allocation)
    static cudaStream_t s2 = nullptr;
    static cudaEvent_t evFork = nullptr, evX = nullptr, evW = nullptr, evT = nullptr;
    if (!s2) {
        cudaStreamCreateWithFlags(&s2, cudaStreamNonBlocking);
        cudaEventCreateWithFlags(&evFork, cudaEventDisableTiming);
        cudaEventCreateWithFlags(&evX,    cudaEventDisableTiming);
        cudaEventCreateWithFlags(&evW,    cudaEventDisableTiming);
        cudaEventCreateWithFlags(&evT,    cudaEventDisableTiming);
    }

    const float scale = 1.0f / 32.0f;  // 1/sqrt(1024)
    const int nx = BATCH * NSEQ * FDIM;

    const long long sX = (long long)NSEQ * FDIM;
    const long long sT = (long long)NSEQ * LDIM;
    const long long sC = (long long)FDIM * FDIM;
    const long long sP = (long long)LDIM * FDIM;
    const long long sQ = (long long)ODIM * LDIM;

    // ---- stream 0: x conversion (launch #0) ----
    cudaEventRecord(evFork, 0);                      // fork point for s2
    conv_x_kernel<<<nx / 8 / 256, 256>>>((const float4*)x, (__nv_bfloat162*)xh, (__nv_bfloat162*)xl);
    cudaEventRecord(evX, 0);

    // ---- stream s2: weight conversions (launches #1-3), then theta (#4) ----
    cudaStreamWaitEvent(s2, evFork, 0);
    conv_pair_kernel<<<(LDIM * FDIM) / 256, 256, 0, s2>>>(Wt, Wth, Wtl, LDIM * FDIM);
    conv_pair_kernel<<<(LDIM * FDIM) / 256, 256, 0, s2>>>(Wp, Wph, Wpl, LDIM * FDIM);
    conv_pair_kernel<<<(ODIM * FDIM) / 256, 256, 0, s2>>>(Wg, Wgh, Wgl, ODIM * FDIM);
    cudaEventRecord(evW, s2);
    cudaStreamWaitEvent(s2, evX, 0);                 // theta needs xh/xl
    gemm_bf16x3<<<dim3(LDIM / 128, NSEQ / 128, BATCH), 256, GEMM_SMEM, s2>>>(
        xh, xl, Wth, Wtl, nullptr, Th, Tl, LDIM, FDIM, sX, 0, sT, 1.0f, 1);
    cudaEventRecord(evT, s2);

    // ---- stream 0: SYRK (#5: ncu target) -> mirror -> P -> QT ----
    syrk_bf16x3<<<dim3(36, 1, BATCH), 256, GEMM_SMEM>>>(xh, xl, Ch, Cl);
    mirror_kernel<<<dim3(528, BATCH), dim3(32, 8)>>>(Ch, Cl);

    cudaStreamWaitEvent(0, evW, 0);                  // P needs Wph, QT needs Wgh
    gemm_bf16x3<<<dim3(8, 2, BATCH), 256, GEMM_SMEM>>>(
        Wph, Wpl, Ch, Cl, nullptr, Ph, Pl, FDIM, FDIM, 0, sC, sP, scale, 1);
    gemm_bf16x3<<<dim3(2, 8, BATCH), 256, GEMM_SMEM>>>(
        Wgh, Wgl, Ph, Pl, nullptr, Qh, Ql, LDIM, FDIM, 0, sP, sQ, 1.0f, 1);

    // ---- out = theta @ QT^T-form : needs theta (s2) and QT (stream 0) ----
    cudaStreamWaitEvent(0, evT, 0);
    gemm_bf16x3<<<dim3(ODIM / 128, NSEQ / 128, BATCH), 256, GEMM_SMEM>>>(
        Th, Tl, Qh, Ql, out, nullptr, nullptr, ODIM, LDIM, sT, sQ, sX, 1.0f, 0);
}